// round 14
// baseline (speedup 1.0000x reference)
#include <cuda_runtime.h>
#include <cuda_bf16.h>
#include <cuda_fp16.h>
#include <cstdint>

#define HW 1024

// ---------------- scratch (__device__ globals: alloc-guard-safe) ----------------
__device__ float    g_cat  [8u * 1024u * HW];   // 32 MB fp32 (residual path)
__device__ uint16_t g_catH [8u * 1024u * HW];   // 16 MB fp16 shadow
__device__ uint16_t g_qkvH [8u * 768u  * HW];   // fp16 qkv
__device__ float g_scale[2048];
__device__ float g_bias [2048];
__device__ uint16_t g_Whi[2490368];
__device__ uint16_t g_Bhi[18874368];
__device__ uint16_t g_Blo[18874368];

// arena offsets (elements) inside g_Bhi
#define B0_OFF  0u          // generic B buffer (up to K=1024)
#define ZB_OFF  8388608u    // conv output in B-layout [n][256]
#define ATB_OFF 10485760u   // attention output in B-layout [n][256]
#define QT_OFF  12582912    // bf16 attn operands (also in g_Blo)
#define KT_OFF  14680064
#define V_OFF   16777216

// weight arena offsets
#define W_CV1   0
#define W_CONV0 262144
#define W_CONV1 851968
#define W_QKV0  1441792
#define W_QKV1  1638400
#define W_CV2M0 1835008
#define W_CV2M1 1900544
#define W_FIN   1966080
#define W_TOTAL 2490368

__device__ __forceinline__ float silu_f(float v) { return v / (1.f + __expf(-v)); }

__device__ __forceinline__ uint32_t smem_u32(const void* p) {
    uint32_t a;
    asm("{ .reg .u64 t; cvta.to.shared.u64 t, %1; cvt.u32.u64 %0, t; }" : "=r"(a) : "l"(p));
    return a;
}
#define SWZ128(o) ((o) ^ (((o) >> 3) & 0x70))

__device__ __forceinline__ void ldsm_x4(uint32_t* r, uint32_t a) {
    asm volatile("ldmatrix.sync.aligned.m8n8.x4.shared.b16 {%0,%1,%2,%3}, [%4];"
        : "=r"(r[0]), "=r"(r[1]), "=r"(r[2]), "=r"(r[3]) : "r"(a));
}
__device__ __forceinline__ void ldsm_x2(uint32_t* r, uint32_t a) {
    asm volatile("ldmatrix.sync.aligned.m8n8.x2.shared.b16 {%0,%1}, [%2];"
        : "=r"(r[0]), "=r"(r[1]) : "r"(a));
}
__device__ __forceinline__ void mma16816(float* d, const uint32_t* a, const uint32_t* b) {
    asm volatile("mma.sync.aligned.m16n8k16.row.col.f32.bf16.bf16.f32 "
        "{%0,%1,%2,%3}, {%4,%5,%6,%7}, {%8,%9}, {%0,%1,%2,%3};"
        : "+f"(d[0]), "+f"(d[1]), "+f"(d[2]), "+f"(d[3])
        : "r"(a[0]), "r"(a[1]), "r"(a[2]), "r"(a[3]), "r"(b[0]), "r"(b[1]));
}
__device__ __forceinline__ void mma16816f(float* d, const uint32_t* a, const uint32_t* b) {
    asm volatile("mma.sync.aligned.m16n8k16.row.col.f32.f16.f16.f32 "
        "{%0,%1,%2,%3}, {%4,%5,%6,%7}, {%8,%9}, {%0,%1,%2,%3};"
        : "+f"(d[0]), "+f"(d[1]), "+f"(d[2]), "+f"(d[3])
        : "r"(a[0]), "r"(a[1]), "r"(a[2]), "r"(a[3]), "r"(b[0]), "r"(b[1]));
}
__device__ __forceinline__ void cpa16(uint32_t d, const void* s) {
    asm volatile("cp.async.cg.shared.global [%0], [%1], 16;" :: "r"(d), "l"(s));
}
__device__ __forceinline__ void cpa16z(uint32_t d, const void* s, int sz) {
    asm volatile("cp.async.cg.shared.global [%0], [%1], 16, %2;" :: "r"(d), "l"(s), "r"(sz));
}
#define CPA_COMMIT() asm volatile("cp.async.commit_group;" ::: "memory")
#define CPA_WAIT1()  asm volatile("cp.async.wait_group 1;" ::: "memory")
#define CPA_WAIT0()  asm volatile("cp.async.wait_group 0;" ::: "memory")

__device__ __forceinline__ uint32_t packbf(float lo, float hi) {
    uint32_t r;
    asm("cvt.rn.bf16x2.f32 %0, %1, %2;" : "=r"(r) : "f"(hi), "f"(lo));
    return r;
}

// ---------------- BN fold ----------------
__global__ void fold_bn_kernel(const float* __restrict__ cv1, const float* __restrict__ cv2,
                               const float* __restrict__ mcv1, const float* __restrict__ mcv2)
{
    int c = blockIdx.x * 256 + threadIdx.x;
    if (c >= 2048) return;
    const float* p; int C, lc;
    if (c < 512)        { p = cv1;  C = 512; lc = c; }
    else if (c < 1024)  { p = cv2;  C = 512; lc = c - 512; }
    else if (c < 1536)  { int i = (c - 1024) >> 8; p = mcv1 + i * 1024; C = 256; lc = (c - 1024) & 255; }
    else                { int i = (c - 1536) >> 8; p = mcv2 + i * 1024; C = 256; lc = (c - 1536) & 255; }
    float g = p[lc], b = p[C + lc], m = p[2 * C + lc], v = p[3 * C + lc];
    float s = g / sqrtf(v + 1e-3f);
    g_scale[c] = s;
    g_bias[c]  = b - m * s;
}

// ---------------- fused weight converter: all weights fp32 -> fp16 ----------------
__global__ void convW_all_kernel(const float* __restrict__ cv1w, const float* __restrict__ mcv1w,
                                 const float* __restrict__ mqkvw, const float* __restrict__ mcv2w,
                                 const float* __restrict__ cv2w,
                                 uint16_t* __restrict__ Whi)
{
    long e = (long)blockIdx.x * 256 + threadIdx.x;
    if (e >= W_TOTAL) return;
    const float* W; long rel; int K; int isConv = 0;
    if (e < W_CONV0)      { W = cv1w; rel = e; K = 512; }
    else if (e < W_QKV0)  { long r = e - W_CONV0; int i = r >= 589824; rel = r - (long)i * 589824;
                            W = mcv1w + (long)i * 589824; K = 2304; isConv = 1; }
    else if (e < W_CV2M0) { long r = e - W_QKV0; int i = r >= 196608; rel = r - (long)i * 196608;
                            W = mqkvw + (long)i * 196608; K = 256; }
    else if (e < W_FIN)   { long r = e - W_CV2M0; int i = r >= 65536; rel = r - (long)i * 65536;
                            W = mcv2w + (long)i * 65536; K = 256; }
    else                  { W = cv2w; rel = e - W_FIN; K = 1024; }
    long m = rel / K, k = rel % K;
    float v;
    if (isConv) { int off = (int)(k >> 8), ci = (int)(k & 255); v = W[m * 2304 + ci * 9 + off]; }
    else v = W[rel];
    Whi[e] = __half_as_ushort(__float2half(v));
}

// ---------------- activation transposer: [b][K][HW] (T) -> fp16 [b][n][K] ----------------
template <typename T>
__global__ void convB_kernel(const T* __restrict__ In, long inStride, int K,
                             uint16_t* __restrict__ Bhi)
{
    __shared__ float t[32][33];
    int n0 = blockIdx.x * 32, k0 = blockIdx.y * 32, b = blockIdx.z;
    int tx = threadIdx.x, ty = threadIdx.y;
    const T* in = In + (long)b * inStride;
#pragma unroll
    for (int yy = 0; yy < 32; yy += 8)
        t[yy + ty][tx] = (float)in[(long)(k0 + yy + ty) * HW + n0 + tx];
    __syncthreads();
#pragma unroll
    for (int yy = 0; yy < 32; yy += 8) {
        int n = n0 + yy + ty, k = k0 + tx;
        float v = t[tx][yy + ty];
        long o = ((long)b * 1024 + n) * K + k;
        Bhi[o] = __half_as_ushort(__float2half(v));
    }
}

// ---------------- warp-MMA GEMM (N-tile 128): fp16, K-chunk 64, 3-stage ----------------
#define MG_STAGE 32768
#define MG_SMEM  98304

__device__ __forceinline__ void mg_load(uint32_t smb, int tid,
    const uint4* __restrict__ wHi, const uint4* __restrict__ bHi,
    int m0, int n0, int K16, int c, uint32_t stOff)
{
    uint32_t sb = smb + stOff;
#pragma unroll
    for (int l = 0; l < 4; l++) {
        int e = tid + l * 256;
        int r = e >> 3, j = e & 7;
        uint32_t off = SWZ128((uint32_t)(r * 128 + j * 16));
        cpa16(sb + off,         wHi + (long)(m0 + r) * K16 + c * 8 + j);
        cpa16(sb + 16384 + off, bHi + (long)(n0 + r) * K16 + c * 8 + j);
    }
}

extern __shared__ char mg_smem[];

__global__ void __launch_bounds__(256, 2) mgemm_kernel(
    const uint16_t* __restrict__ Bhi,
    const uint16_t* __restrict__ Whi,
    int K,
    float* __restrict__ Out, uint16_t* __restrict__ OutH, long outStride,
    const float* __restrict__ scale, const float* __restrict__ bias,
    const float* __restrict__ Res, long resStride,
    int doSilu)
{
    int b = blockIdx.z, m0 = blockIdx.y * 128, n0 = blockIdx.x * 128;
    int tid = threadIdx.x, wid = tid >> 5, lane = tid & 31;
    int warp_m = wid & 1, warp_n = wid >> 1;
    uint32_t smb = smem_u32(mg_smem);

    int K16 = K >> 3;
    const uint4* wHi = (const uint4*)Whi;
    const uint4* bHi = (const uint4*)(Bhi + (long)b * 1024 * K);

    float acc[4][4][4];
#pragma unroll
    for (int i = 0; i < 4; i++)
#pragma unroll
        for (int j = 0; j < 4; j++)
#pragma unroll
            for (int r = 0; r < 4; r++) acc[i][j][r] = 0.f;

    int nChunks = K >> 6;
    mg_load(smb, tid, wHi, bHi, m0, n0, K16, 0, 0);
    CPA_COMMIT();
    if (nChunks > 1) {
        mg_load(smb, tid, wHi, bHi, m0, n0, K16, 1, MG_STAGE);
        CPA_COMMIT();
    }

    int aRowL = warp_m * 64 + (lane & 7) + (lane & 8);
    int aColL = ((lane >> 4) & 1) * 16;
    int bRowX4 = warp_n * 32 + (lane >> 4) * 8 + (lane & 7);
    uint32_t bColX4 = (uint32_t)(((lane >> 3) & 1) * 16);

    int st = 0;
    for (int c = 0; c < nChunks; c++) {
        if (c + 1 < nChunks) { CPA_WAIT1(); } else { CPA_WAIT0(); }
        __syncthreads();
        if (c + 2 < nChunks) {
            int stL = st + 2; if (stL >= 3) stL -= 3;
            mg_load(smb, tid, wHi, bHi, m0, n0, K16, c + 2, (uint32_t)(stL * MG_STAGE));
            CPA_COMMIT();
        }

        uint32_t base = smb + (uint32_t)(st * MG_STAGE);
#pragma unroll
        for (int ks = 0; ks < 4; ks++) {
            uint32_t ah[4][4], bh4[2][4];
#pragma unroll
            for (int mt = 0; mt < 4; mt++)
                ldsm_x4(ah[mt], base + SWZ128((uint32_t)((aRowL + mt * 16) * 128 + aColL + ks * 32)));
#pragma unroll
            for (int p = 0; p < 2; p++)
                ldsm_x4(bh4[p], base + 16384 + SWZ128((uint32_t)((bRowX4 + p * 16) * 128 + bColX4 + ks * 32)));
#pragma unroll
            for (int mt = 0; mt < 4; mt++)
#pragma unroll
                for (int p = 0; p < 2; p++) {
                    mma16816f(acc[mt][2 * p],     ah[mt], &bh4[p][0]);
                    mma16816f(acc[mt][2 * p + 1], ah[mt], &bh4[p][2]);
                }
        }
        st++; if (st >= 3) st = 0;
    }

#pragma unroll
    for (int mt = 0; mt < 4; mt++) {
        int mb = m0 + warp_m * 64 + mt * 16 + (lane >> 2);
#pragma unroll
        for (int h2 = 0; h2 < 2; h2++) {
            int m = mb + h2 * 8;
            float s = 1.f, bb = 0.f;
            if (scale) { s = scale[m]; bb = bias[m]; }
            long rowOff = (long)b * outStride + (long)m * HW;
            long resOff = Res ? ((long)b * resStride + (long)m * HW) : 0;
#pragma unroll
            for (int nt = 0; nt < 4; nt++) {
                int n = n0 + warp_n * 32 + nt * 8 + (lane & 3) * 2;
                float v0 = acc[mt][nt][h2 * 2 + 0] * s + bb;
                float v1 = acc[mt][nt][h2 * 2 + 1] * s + bb;
                if (doSilu) { v0 = silu_f(v0); v1 = silu_f(v1); }
                if (Res) {
                    float2 r2 = *(const float2*)&Res[resOff + n];
                    v0 += r2.x; v1 += r2.y;
                }
                if (Out) *(float2*)&Out[rowOff + n] = make_float2(v0, v1);
                if (OutH) {
                    __half2 hv = __floats2half2_rn(v0, v1);
                    *(__half2*)&OutH[rowOff + n] = hv;
                }
            }
        }
    }
}

// ---------------- warp-MMA GEMM (N-tile 64): fp16, K-chunk 64, 3-stage ----------------
#define MG64_STAGE 24576
#define MG64_SMEM  73728

__device__ __forceinline__ void mg64_load(uint32_t smb, int tid,
    const uint4* __restrict__ wHi, const uint4* __restrict__ bHi,
    int m0, int n0, int K16, int c, uint32_t stOff)
{
    uint32_t sb = smb + stOff;
#pragma unroll
    for (int l = 0; l < 4; l++) {
        int e = tid + l * 256;
        int r = e >> 3, j = e & 7;
        uint32_t off = SWZ128((uint32_t)(r * 128 + j * 16));
        cpa16(sb + off, wHi + (long)(m0 + r) * K16 + c * 8 + j);
    }
#pragma unroll
    for (int l = 0; l < 2; l++) {
        int e = tid + l * 256;
        int r = e >> 3, j = e & 7;
        uint32_t off = SWZ128((uint32_t)(r * 128 + j * 16));
        cpa16(sb + 16384 + off, bHi + (long)(n0 + r) * K16 + c * 8 + j);
    }
}

// implicit 3x3 conv B loader: B is yi in fp16 [n][256]; chunk c (64 wide) -> tap (c>>2), quarter (c&3)
__device__ __forceinline__ void mgc_load(uint32_t smb, int tid,
    const uint4* __restrict__ wHi, const uint4* __restrict__ bHi,
    int m0, int n0, int K16, int c, uint32_t stOff)
{
    uint32_t sb = smb + stOff;
#pragma unroll
    for (int l = 0; l < 4; l++) {
        int e = tid + l * 256;
        int r = e >> 3, j = e & 7;
        uint32_t off = SWZ128((uint32_t)(r * 128 + j * 16));
        cpa16(sb + off, wHi + (long)(m0 + r) * K16 + c * 8 + j);
    }
    int tap = c >> 2, q = c & 3;
    int dy = tap / 3 - 1, dx = tap % 3 - 1;
#pragma unroll
    for (int l = 0; l < 2; l++) {
        int e = tid + l * 256;
        int r = e >> 3, j = e & 7;
        int pix = n0 + r;
        int y = (pix >> 5) + dy, x = (pix & 31) + dx;
        bool ok = ((unsigned)y < 32u) && ((unsigned)x < 32u);
        int ps = ok ? (y * 32 + x) : 0;
        int sz = ok ? 16 : 0;
        uint32_t off = SWZ128((uint32_t)(r * 128 + j * 16));
        cpa16z(sb + 16384 + off, bHi + (long)ps * 32 + q * 8 + j, sz);
    }
}

template <int CONV>
__global__ void __launch_bounds__(256, 2) mgemm64_kernel_t(
    const uint16_t* __restrict__ Bhi,
    const uint16_t* __restrict__ Whi,
    int K, int bK,
    float* __restrict__ Out, uint16_t* __restrict__ OutH, long outStride,
    uint16_t* __restrict__ OutB,
    const float* __restrict__ scale, const float* __restrict__ bias,
    const float* __restrict__ Res, long resStride,
    int doSilu)
{
    int b = blockIdx.z, m0 = blockIdx.y * 128, n0 = blockIdx.x * 64;
    int tid = threadIdx.x, wid = tid >> 5, lane = tid & 31;
    int warp_m = wid & 3, warp_n = wid >> 2;
    uint32_t smb = smem_u32(mg_smem);

    int K16 = K >> 3;
    const uint4* wHi = (const uint4*)Whi;
    const uint4* bHi = (const uint4*)(Bhi + (long)b * 1024 * bK);

    float acc[2][4][4];
#pragma unroll
    for (int i = 0; i < 2; i++)
#pragma unroll
        for (int j = 0; j < 4; j++)
#pragma unroll
            for (int r = 0; r < 4; r++) acc[i][j][r] = 0.f;

    int nChunks = K >> 6;
    if (CONV) mgc_load(smb, tid, wHi, bHi, m0, n0, K16, 0, 0);
    else      mg64_load(smb, tid, wHi, bHi, m0, n0, K16, 0, 0);
    CPA_COMMIT();
    if (nChunks > 1) {
        if (CONV) mgc_load(smb, tid, wHi, bHi, m0, n0, K16, 1, MG64_STAGE);
        else      mg64_load(smb, tid, wHi, bHi, m0, n0, K16, 1, MG64_STAGE);
        CPA_COMMIT();
    }

    int aRowL = warp_m * 32 + (lane & 7) + (lane & 8);
    int aColL = ((lane >> 4) & 1) * 16;
    int bRowX4 = warp_n * 32 + (lane >> 4) * 8 + (lane & 7);
    uint32_t bColX4 = (uint32_t)(((lane >> 3) & 1) * 16);

    int st = 0;
    for (int c = 0; c < nChunks; c++) {
        if (c + 1 < nChunks) { CPA_WAIT1(); } else { CPA_WAIT0(); }
        __syncthreads();
        if (c + 2 < nChunks) {
            int stL = st + 2; if (stL >= 3) stL -= 3;
            if (CONV) mgc_load(smb, tid, wHi, bHi, m0, n0, K16, c + 2, (uint32_t)(stL * MG64_STAGE));
            else      mg64_load(smb, tid, wHi, bHi, m0, n0, K16, c + 2, (uint32_t)(stL * MG64_STAGE));
            CPA_COMMIT();
        }

        uint32_t base = smb + (uint32_t)(st * MG64_STAGE);
#pragma unroll
        for (int ks = 0; ks < 4; ks++) {
            uint32_t ah[2][4], bh4[2][4];
#pragma unroll
            for (int mt = 0; mt < 2; mt++)
                ldsm_x4(ah[mt], base + SWZ128((uint32_t)((aRowL + mt * 16) * 128 + aColL + ks * 32)));
#pragma unroll
            for (int p = 0; p < 2; p++)
                ldsm_x4(bh4[p], base + 16384 + SWZ128((uint32_t)((bRowX4 + p * 16) * 128 + bColX4 + ks * 32)));
#pragma unroll
            for (int mt = 0; mt < 2; mt++)
#pragma unroll
                for (int p = 0; p < 2; p++) {
                    mma16816f(acc[mt][2 * p],     ah[mt], &bh4[p][0]);
                    mma16816f(acc[mt][2 * p + 1], ah[mt], &bh4[p][2]);
                }
        }
        st++; if (st >= 3) st = 0;
    }

    float* stage = (float*)mg_smem;   // [64][132] when OutB (33 KB < 72 KB)
    if (OutB) __syncthreads();

#pragma unroll
    for (int mt = 0; mt < 2; mt++) {
        int mlB = warp_m * 32 + mt * 16 + (lane >> 2);
#pragma unroll
        for (int h2 = 0; h2 < 2; h2++) {
            int ml = mlB + h2 * 8;
            int m = m0 + ml;
            float s = 1.f, bb = 0.f;
            if (scale) { s = scale[m]; bb = bias[m]; }
            long rowOff = (long)b * outStride + (long)m * HW;
            long resOff = Res ? ((long)b * resStride + (long)m * HW) : 0;
#pragma unroll
            for (int nt = 0; nt < 4; nt++) {
                int nl = warp_n * 32 + nt * 8 + (lane & 3) * 2;
                int n = n0 + nl;
                float v0 = acc[mt][nt][h2 * 2 + 0] * s + bb;
                float v1 = acc[mt][nt][h2 * 2 + 1] * s + bb;
                if (doSilu) { v0 = silu_f(v0); v1 = silu_f(v1); }
                if (Res) {
                    float2 r2 = *(const float2*)&Res[resOff + n];
                    v0 += r2.x; v1 += r2.y;
                }
                if (Out) *(float2*)&Out[rowOff + n] = make_float2(v0, v1);
                if (OutH) {
                    __half2 hv = __floats2half2_rn(v0, v1);
                    *(__half2*)&OutH[rowOff + n] = hv;
                }
                if (OutB) {
                    stage[nl * 132 + ml] = v0;
                    stage[(nl + 1) * 132 + ml] = v1;
                }
            }
        }
    }

    if (OutB) {
        __syncthreads();
        for (int e = tid; e < 4096; e += 256) {
            int row = e >> 6, c2 = e & 63;
            float v0 = stage[row * 132 + c2 * 2];
            float v1 = stage[row * 132 + c2 * 2 + 1];
            __half2 hv = __floats2half2_rn(v0, v1);
            *(__half2*)&OutB[((long)b * 1024 + n0 + row) * 256 + m0 + c2 * 2] = hv;
        }
    }
}

// ---------------- attention converter: qkv fp16 -> qT/kT(+relpos)/v bf16 hi/lo ----------------
__global__ void convAttn_kernel(const uint16_t* __restrict__ QKVH,
                                const float* __restrict__ RW, const float* __restrict__ RH,
                                __nv_bfloat16* __restrict__ Hi, __nv_bfloat16* __restrict__ Lo)
{
    __shared__ float tq[32][33], tk[32][33];
    int it = blockIdx.x, dt = blockIdx.y, bh = blockIdx.z;
    int b = bh >> 2, hh = bh & 3;
    int tx = threadIdx.x, ty = threadIdx.y;
    const __half* base = (const __half*)QKVH + (long)b * 768 * HW;
#pragma unroll
    for (int l = 0; l < 4; l++) {
        int d = dt * 32 + ty + l * 8;
        int ch = hh * 64 + d;
        float qv = __half2float(base[(long)ch * HW + it * 32 + tx]) * 0.125f;
        float kv = __half2float(base[(long)(256 + ch) * HW + it * 32 + tx]) + RW[ch * 32 + tx] + RH[ch * 32 + it];
        float vv = __half2float(base[(long)(512 + ch) * HW + it * 32 + tx]);
        tq[ty + l * 8][tx] = qv;
        tk[ty + l * 8][tx] = kv;
        long vo = V_OFF + ((long)bh * 64 + d) * 1024 + it * 32 + tx;
        __nv_bfloat16 vh = __float2bfloat16(vv);
        Hi[vo] = vh;
        Lo[vo] = __float2bfloat16(vv - __bfloat162float(vh));
    }
    __syncthreads();
#pragma unroll
    for (int l = 0; l < 4; l++) {
        int i = it * 32 + ty + l * 8;
        int d = dt * 32 + tx;
        float qv = tq[tx][ty + l * 8];
        float kv = tk[tx][ty + l * 8];
        long qo = ((long)bh * 1024 + i) * 64 + d;
        __nv_bfloat16 qh = __float2bfloat16(qv);
        Hi[QT_OFF + qo] = qh;
        Lo[QT_OFF + qo] = __float2bfloat16(qv - __bfloat162float(qh));
        __nv_bfloat16 kh = __float2bfloat16(kv);
        Hi[KT_OFF + qo] = kh;
        Lo[KT_OFF + qo] = __float2bfloat16(kv - __bfloat162float(kh));
    }
}

// ---------------- MMA flash attention (bf16 split-3), emits B-layout fp16 ----------------
#define AT_SMEM 163840

__device__ __forceinline__ void kv_load(uint32_t smb, int tid,
    const __nv_bfloat16* __restrict__ kTh, const __nv_bfloat16* __restrict__ kTl,
    const __nv_bfloat16* __restrict__ vH, const __nv_bfloat16* __restrict__ vL,
    int bh, int t, uint32_t stOff)
{
    uint32_t kb = smb + stOff;
    const uint4* kh4 = (const uint4*)(kTh + ((long)bh * 1024 + t * 128) * 64);
    const uint4* kl4 = (const uint4*)(kTl + ((long)bh * 1024 + t * 128) * 64);
    int r = tid >> 1, j0 = (tid & 1) * 4;
#pragma unroll
    for (int j = 0; j < 4; j++) {
        uint32_t off = SWZ128((uint32_t)(r * 128 + (j0 + j) * 16));
        cpa16(kb + off, kh4 + (long)r * 8 + j0 + j);
        cpa16(kb + 16384 + off, kl4 + (long)r * 8 + j0 + j);
    }
    const uint4* vh4 = (const uint4*)(vH + (long)bh * 65536 + t * 128);
    const uint4* vl4 = (const uint4*)(vL + (long)bh * 65536 + t * 128);
    int d = tid >> 2, jc0 = (tid & 3) * 4;
#pragma unroll
    for (int j = 0; j < 4; j++) {
        int jc = jc0 + j;
        uint32_t off = (uint32_t)((jc >> 3) * 8192) + SWZ128((uint32_t)(d * 128 + (jc & 7) * 16));
        cpa16(kb + 32768 + off, vh4 + (long)d * 128 + jc);
        cpa16(kb + 49152 + off, vl4 + (long)d * 128 + jc);
    }
}

extern __shared__ char at_smem[];

__global__ void __launch_bounds__(256) attn_mma_kernel(
    const __nv_bfloat16* __restrict__ Hi, const __nv_bfloat16* __restrict__ Lo,
    uint16_t* __restrict__ OutB)
{
    int qt = blockIdx.x, h = blockIdx.y, b = blockIdx.z;
    int bh = b * 4 + h;
    int tid = threadIdx.x, wid = tid >> 5, lane = tid & 31, li = lane & 15;
    uint32_t smb = smem_u32(at_smem);

    const __nv_bfloat16* qTh = Hi + QT_OFF;
    const __nv_bfloat16* qTl = Lo + QT_OFF;
    const __nv_bfloat16* kTh = Hi + KT_OFF;
    const __nv_bfloat16* kTl = Lo + KT_OFF;
    const __nv_bfloat16* vH  = Hi + V_OFF;
    const __nv_bfloat16* vL  = Lo + V_OFF;

    {
        const uint4* qh4 = (const uint4*)(qTh + ((long)bh * 1024 + qt * 128) * 64);
        const uint4* ql4 = (const uint4*)(qTl + ((long)bh * 1024 + qt * 128) * 64);
        int r = tid >> 1, j0 = (tid & 1) * 4;
        uint32_t qb = smb + 131072;
#pragma unroll
        for (int j = 0; j < 4; j++) {
            uint32_t off = SWZ128((uint32_t)(r * 128 + (j0 + j) * 16));
            cpa16(qb + off, qh4 + (long)r * 8 + j0 + j);
            cpa16(qb + 16384 + off, ql4 + (long)r * 8 + j0 + j);
        }
    }
    CPA_COMMIT();
    kv_load(smb, tid, kTh, kTl, vH, vL, bh, 0, 0);
    CPA_COMMIT();
    CPA_WAIT1();
    __syncthreads();

    uint32_t qfh[4][4], qfl[4][4];
    {
        int aRow = wid * 16 + (lane & 7) + (lane & 8);
        int aCol = ((lane >> 4) & 1) * 16;
#pragma unroll
        for (int ks = 0; ks < 4; ks++) {
            uint32_t off = SWZ128((uint32_t)(aRow * 128 + aCol + ks * 32));
            ldsm_x4(qfh[ks], smb + 131072 + off);
            ldsm_x4(qfl[ks], smb + 131072 + 16384 + off);
        }
    }

    float oacc[8][4];
#pragma unroll
    for (int i = 0; i < 8; i++)
#pragma unroll
        for (int j = 0; j < 4; j++) oacc[i][j] = 0.f;
    float m0 = -1e30f, m1 = -1e30f, l0 = 0.f, l1 = 0.f;

    int sRowX4 = (lane >> 4) * 8 + (lane & 7);
    uint32_t sColX4 = (uint32_t)(((lane >> 3) & 1) * 16);

    for (int t = 0; t < 8; t++) {
        int s = t & 1;
        if (t < 7) {
            kv_load(smb, tid, kTh, kTl, vH, vL, bh, t + 1, (uint32_t)((s ^ 1) * 65536));
            CPA_COMMIT();
            CPA_WAIT1();
        } else {
            CPA_WAIT0();
        }
        __syncthreads();

        uint32_t kb = smb + s * 65536;
        float sacc[16][4];
#pragma unroll
        for (int i = 0; i < 16; i++)
#pragma unroll
            for (int j = 0; j < 4; j++) sacc[i][j] = 0.f;

#pragma unroll
        for (int p = 0; p < 8; p++) {
            int rowB = p * 16 + sRowX4;
#pragma unroll
            for (int ks = 0; ks < 4; ks++) {
                uint32_t off = SWZ128((uint32_t)(rowB * 128 + sColX4 + ks * 32));
                uint32_t kh4[4], kl4[4];
                ldsm_x4(kh4, kb + off);
                ldsm_x4(kl4, kb + 16384 + off);
                mma16816(sacc[2 * p],     qfh[ks], &kh4[0]);
                mma16816(sacc[2 * p + 1], qfh[ks], &kh4[2]);
                mma16816(sacc[2 * p],     qfl[ks], &kh4[0]);
                mma16816(sacc[2 * p + 1], qfl[ks], &kh4[2]);
                mma16816(sacc[2 * p],     qfh[ks], &kl4[0]);
                mma16816(sacc[2 * p + 1], qfh[ks], &kl4[2]);
            }
        }

        float mx0 = m0, mx1 = m1;
#pragma unroll
        for (int nt = 0; nt < 16; nt++) {
            mx0 = fmaxf(mx0, fmaxf(sacc[nt][0], sacc[nt][1]));
            mx1 = fmaxf(mx1, fmaxf(sacc[nt][2], sacc[nt][3]));
        }
        mx0 = fmaxf(mx0, __shfl_xor_sync(0xffffffffu, mx0, 1));
        mx0 = fmaxf(mx0, __shfl_xor_sync(0xffffffffu, mx0, 2));
        mx1 = fmaxf(mx1, __shfl_xor_sync(0xffffffffu, mx1, 1));
        mx1 = fmaxf(mx1, __shfl_xor_sync(0xffffffffu, mx1, 2));
        float a0 = __expf(m0 - mx0), a1 = __expf(m1 - mx1);
        m0 = mx0; m1 = mx1;

        float ls0 = 0.f, ls1 = 0.f;
        uint32_t pah[8][4], pal[8][4];
#pragma unroll
        for (int kj = 0; kj < 8; kj++) {
            float p00 = __expf(sacc[2 * kj][0] - m0);
            float p01 = __expf(sacc[2 * kj][1] - m0);
            float p02 = __expf(sacc[2 * kj][2] - m1);
            float p03 = __expf(sacc[2 * kj][3] - m1);
            float p10 = __expf(sacc[2 * kj + 1][0] - m0);
            float p11 = __expf(sacc[2 * kj + 1][1] - m0);
            float p12 = __expf(sacc[2 * kj + 1][2] - m1);
            float p13 = __expf(sacc[2 * kj + 1][3] - m1);
            ls0 += p00 + p01 + p10 + p11;
            ls1 += p02 + p03 + p12 + p13;
            pah[kj][0] = packbf(p00, p01);
            pah[kj][1] = packbf(p02, p03);
            pah[kj][2] = packbf(p10, p11);
            pah[kj][3] = packbf(p12, p13);
            float q00 = p00 - __bfloat162float(__float2bfloat16(p00));
            float q01 = p01 - __bfloat162float(__float2bfloat16(p01));
            float q02 = p02 - __bfloat162float(__float2bfloat16(p02));
            float q03 = p03 - __bfloat162float(__float2bfloat16(p03));
            float q10 = p10 - __bfloat162float(__float2bfloat16(p10));
            float q11 = p11 - __bfloat162float(__float2bfloat16(p11));
            float q12 = p12 - __bfloat162float(__float2bfloat16(p12));
            float q13 = p13 - __bfloat162float(__float2bfloat16(p13));
            pal[kj][0] = packbf(q00, q01);
            pal[kj][1] = packbf(q02, q03);
            pal[kj][2] = packbf(q10, q11);
            pal[kj][3] = packbf(q12, q13);
        }
        ls0 += __shfl_xor_sync(0xffffffffu, ls0, 1);
        ls0 += __shfl_xor_sync(0xffffffffu, ls0, 2);
        ls1 += __shfl_xor_sync(0xffffffffu, ls1, 1);
        ls1 += __shfl_xor_sync(0xffffffffu, ls1, 2);
        l0 = l0 * a0 + ls0;
        l1 = l1 * a1 + ls1;
#pragma unroll
        for (int dt = 0; dt < 8; dt++) {
            oacc[dt][0] *= a0; oacc[dt][1] *= a0;
            oacc[dt][2] *= a1; oacc[dt][3] *= a1;
        }

#pragma unroll
        for (int dt = 0; dt < 8; dt++) {
            int rowV = dt * 8 + (li & 7);
#pragma unroll
            for (int kj = 0; kj < 8; kj++) {
                uint32_t off = (uint32_t)((kj >> 2) * 8192) +
                               SWZ128((uint32_t)(rowV * 128 + (li >> 3) * 16 + (kj & 3) * 32));
                uint32_t vh2[2], vl2[2];
                ldsm_x2(vh2, kb + 32768 + off);
                ldsm_x2(vl2, kb + 49152 + off);
                mma16816(oacc[dt], pah[kj], vh2);
                mma16816(oacc[dt], pal[kj], vh2);
                mma16816(oacc[dt], pah[kj], vl2);
            }
        }
        __syncthreads();
    }

    float i0 = 1.f / l0, i1 = 1.f / l1;
    float* stg = (float*)at_smem;   // [128][66]
    int r0 = wid * 16 + (lane >> 2);
#pragma unroll
    for (int dt = 0; dt < 8; dt++) {
        int d = dt * 8 + (lane & 3) * 2;
        stg[r0 * 66 + d]           = oacc[dt][0] * i0;
        stg[r0 * 66 + d + 1]       = oacc[dt][1] * i0;
        stg[(r0 + 8) * 66 + d]     = oacc[dt][2] * i1;
        stg[(r0 + 8) * 66 + d + 1] = oacc[dt][3] * i1;
    }
    __syncthreads();
    // emit B-layout fp16: [n = global token][k = 256 channels]
    for (int e = tid; e < 4096; e += 256) {
        int i = e >> 5, dp = (e & 31) * 2;
        __half2 hv = __floats2half2_rn(stg[i * 66 + dp], stg[i * 66 + dp + 1]);
        *(__half2*)&OutB[((long)b * 1024 + qt * 128 + i) * 256 + h * 64 + dp] = hv;
    }
}

// ---------------- launch ----------------
extern "C" void kernel_launch(void* const* d_in, const int* in_sizes, int n_in,
                              void* d_out, int out_size)
{
    const float* x      = (const float*)d_in[0];
    const float* cv1_w  = (const float*)d_in[1];
    const float* cv1_bn = (const float*)d_in[2];
    const float* cv2_w  = (const float*)d_in[3];
    const float* cv2_bn = (const float*)d_in[4];
    const float* mcv1w  = (const float*)d_in[5];
    const float* mcv1bn = (const float*)d_in[6];
    const float* mqkvw  = (const float*)d_in[7];
    const float* mrw    = (const float*)d_in[8];
    const float* mrh    = (const float*)d_in[9];
    const float* mcv2w  = (const float*)d_in[10];
    const float* mcv2bn = (const float*)d_in[11];
    float* out = (float*)d_out;

    float *cat, *scl, *bia;
    uint16_t *catH, *qkvH, *whi, *bhi, *blo;
    cudaGetSymbolAddress((void**)&cat,   g_cat);
    cudaGetSymbolAddress((void**)&catH,  g_catH);
    cudaGetSymbolAddress((void**)&qkvH,  g_qkvH);
    cudaGetSymbolAddress((void**)&scl,   g_scale);
    cudaGetSymbolAddress((void**)&bia,   g_bias);
    cudaGetSymbolAddress((void**)&whi,   g_Whi);
    cudaGetSymbolAddress((void**)&bhi,   g_Bhi);
    cudaGetSymbolAddress((void**)&blo,   g_Blo);
    __nv_bfloat16* bhiB = (__nv_bfloat16*)bhi;
    __nv_bfloat16* bloB = (__nv_bfloat16*)blo;

    cudaFuncSetAttribute(mgemm_kernel, cudaFuncAttributeMaxDynamicSharedMemorySize, MG_SMEM);
    cudaFuncSetAttribute(mgemm64_kernel_t<0>, cudaFuncAttributeMaxDynamicSharedMemorySize, MG64_SMEM);
    cudaFuncSetAttribute(mgemm64_kernel_t<1>, cudaFuncAttributeMaxDynamicSharedMemorySize, MG64_SMEM);
    cudaFuncSetAttribute(attn_mma_kernel, cudaFuncAttributeMaxDynamicSharedMemorySize, AT_SMEM);

    fold_bn_kernel<<<8, 256>>>(cv1_bn, cv2_bn, mcv1bn, mcv2bn);
    convW_all_kernel<<<(W_TOTAL + 255) / 256, 256>>>(cv1_w, mcv1w, mqkvw, mcv2w, cv2_w, whi);

    // ---- cv1: 512 -> 512, BN+SiLU -> fp32 cat[0:512) + fp16 catH[0:512) ----
    convB_kernel<float><<<dim3(32, 16, 8), dim3(32, 8)>>>(x, (long)512 * HW, 512, bhi + B0_OFF);
    mgemm_kernel<<<dim3(8, 4, 8), 256, MG_SMEM>>>(
        bhi + B0_OFF, whi + W_CV1, 512, cat, catH, (long)1024 * HW,
        scl + 0, bia + 0, nullptr, 0, 1);

    for (int i = 0; i < 2; i++) {
        long yin  = (long)(i == 0 ? 256 : 512) * HW;
        long yout = (long)(512 + i * 256) * HW;
        long wConv = i ? W_CONV1 : W_CONV0;
        long wQkv  = i ? W_QKV1  : W_QKV0;
        long wCv2  = i ? W_CV2M1 : W_CV2M0;

        // z = cbs(yi, 3x3) as IMPLICIT GEMM; emits fp16 B-layout ZB directly
        convB_kernel<__half><<<dim3(32, 8, 8), dim3(32, 8)>>>(
            (const __half*)(catH + yin), (long)1024 * HW, 256, bhi + B0_OFF);
        mgemm64_kernel_t<1><<<dim3(16, 2, 8), 256, MG64_SMEM>>>(
            bhi + B0_OFF, whi + wConv, 2304, 256,
            nullptr, nullptr, 0, bhi + ZB_OFF,
            scl + 1024 + i * 256, bia + 1024 + i * 256, nullptr, 0, 1);

        // qkv = conv1x1(z), 256 -> 768 (reads ZB directly); output fp16 qkvH
        mgemm_kernel<<<dim3(8, 6, 8), 256, MG_SMEM>>>(
            bhi + ZB_OFF, whi + wQkv, 256, nullptr, qkvH, (long)768 * HW,
            nullptr, nullptr, nullptr, 0, 0);

        // attention operand conversion + MMA flash attention -> fp16 B-layout ATB
        convAttn_kernel<<<dim3(32, 2, 32), dim3(32, 8)>>>(
            qkvH, mrw + (long)i * 8192, mrh + (long)i * 8192, bhiB, bloB);
        attn_mma_kernel<<<dim3(8, 4, 8), 256, AT_SMEM>>>(bhiB, bloB, bhi + ATB_OFF);

        // y_{i+2} = yi + silu(bn(conv1x1(attn))) (reads ATB) -> fp32 cat + fp16 catH
        mgemm64_kernel_t<0><<<dim3(16, 2, 8), 256, MG64_SMEM>>>(
            bhi + ATB_OFF, whi + wCv2, 256, 256,
            cat + yout, catH + yout, (long)1024 * HW, nullptr,
            scl + 1536 + i * 256, bia + 1536 + i * 256, cat + yin, (long)1024 * HW, 1);
    }

    // ---- final: 1024 -> 512, BN+SiLU, fp32 out ----
    convB_kernel<__half><<<dim3(32, 32, 8), dim3(32, 8)>>>(
        (const __half*)catH, (long)1024 * HW, 1024, bhi + B0_OFF);
    mgemm_kernel<<<dim3(8, 4, 8), 256, MG_SMEM>>>(
        bhi + B0_OFF, whi + W_FIN, 1024, out, nullptr, (long)512 * HW,
        scl + 512, bia + 512, nullptr, 0, 1);
}

// round 15
// speedup vs baseline: 1.2033x; 1.2033x over previous
#include <cuda_runtime.h>
#include <cuda_bf16.h>
#include <cuda_fp16.h>
#include <cstdint>

#define HW 1024

// ---------------- scratch (__device__ globals: alloc-guard-safe) ----------------
__device__ float    g_cat  [8u * 1024u * HW];   // 32 MB fp32 (residual path)
__device__ uint16_t g_catH [8u * 1024u * HW];   // 16 MB fp16 shadow
__device__ uint16_t g_qkvH [8u * 768u  * HW];   // fp16 qkv
__device__ float g_scale[2048];
__device__ float g_bias [2048];
__device__ uint16_t g_Whi[2490368];
__device__ uint16_t g_Bhi[18874368];
__device__ uint16_t g_Blo[2097152];             // only Q-lo now

// arena offsets (elements) inside g_Bhi
#define B0_OFF  0u          // generic B buffer (up to K=1024)
#define ZB_OFF  8388608u    // conv output in B-layout [n][256]
#define ATB_OFF 10485760u   // attention output in B-layout [n][256]
#define QT_OFF  12582912    // fp16 Q hi (Q lo lives in g_Blo at offset 0)
#define KT_OFF  14680064    // fp16 K (+relpos)
#define V_OFF   16777216    // fp16 V

// weight arena offsets
#define W_CV1   0
#define W_CONV0 262144
#define W_CONV1 851968
#define W_QKV0  1441792
#define W_QKV1  1638400
#define W_CV2M0 1835008
#define W_CV2M1 1900544
#define W_FIN   1966080
#define W_TOTAL 2490368

__device__ __forceinline__ float silu_f(float v) { return v / (1.f + __expf(-v)); }

__device__ __forceinline__ uint32_t smem_u32(const void* p) {
    uint32_t a;
    asm("{ .reg .u64 t; cvta.to.shared.u64 t, %1; cvt.u32.u64 %0, t; }" : "=r"(a) : "l"(p));
    return a;
}
#define SWZ128(o) ((o) ^ (((o) >> 3) & 0x70))

__device__ __forceinline__ void ldsm_x4(uint32_t* r, uint32_t a) {
    asm volatile("ldmatrix.sync.aligned.m8n8.x4.shared.b16 {%0,%1,%2,%3}, [%4];"
        : "=r"(r[0]), "=r"(r[1]), "=r"(r[2]), "=r"(r[3]) : "r"(a));
}
__device__ __forceinline__ void ldsm_x2(uint32_t* r, uint32_t a) {
    asm volatile("ldmatrix.sync.aligned.m8n8.x2.shared.b16 {%0,%1}, [%2];"
        : "=r"(r[0]), "=r"(r[1]) : "r"(a));
}
__device__ __forceinline__ void mma16816f(float* d, const uint32_t* a, const uint32_t* b) {
    asm volatile("mma.sync.aligned.m16n8k16.row.col.f32.f16.f16.f32 "
        "{%0,%1,%2,%3}, {%4,%5,%6,%7}, {%8,%9}, {%0,%1,%2,%3};"
        : "+f"(d[0]), "+f"(d[1]), "+f"(d[2]), "+f"(d[3])
        : "r"(a[0]), "r"(a[1]), "r"(a[2]), "r"(a[3]), "r"(b[0]), "r"(b[1]));
}
__device__ __forceinline__ void cpa16(uint32_t d, const void* s) {
    asm volatile("cp.async.cg.shared.global [%0], [%1], 16;" :: "r"(d), "l"(s));
}
__device__ __forceinline__ void cpa16z(uint32_t d, const void* s, int sz) {
    asm volatile("cp.async.cg.shared.global [%0], [%1], 16, %2;" :: "r"(d), "l"(s), "r"(sz));
}
#define CPA_COMMIT() asm volatile("cp.async.commit_group;" ::: "memory")
#define CPA_WAIT1()  asm volatile("cp.async.wait_group 1;" ::: "memory")
#define CPA_WAIT0()  asm volatile("cp.async.wait_group 0;" ::: "memory")

// pack two floats into fp16x2 (lo in low half)
__device__ __forceinline__ uint32_t packh(float lo, float hi) {
    __half2 h = __floats2half2_rn(lo, hi);
    return *(uint32_t*)&h;
}

// ---------------- BN fold ----------------
__global__ void fold_bn_kernel(const float* __restrict__ cv1, const float* __restrict__ cv2,
                               const float* __restrict__ mcv1, const float* __restrict__ mcv2)
{
    int c = blockIdx.x * 256 + threadIdx.x;
    if (c >= 2048) return;
    const float* p; int C, lc;
    if (c < 512)        { p = cv1;  C = 512; lc = c; }
    else if (c < 1024)  { p = cv2;  C = 512; lc = c - 512; }
    else if (c < 1536)  { int i = (c - 1024) >> 8; p = mcv1 + i * 1024; C = 256; lc = (c - 1024) & 255; }
    else                { int i = (c - 1536) >> 8; p = mcv2 + i * 1024; C = 256; lc = (c - 1536) & 255; }
    float g = p[lc], b = p[C + lc], m = p[2 * C + lc], v = p[3 * C + lc];
    float s = g / sqrtf(v + 1e-3f);
    g_scale[c] = s;
    g_bias[c]  = b - m * s;
}

// ---------------- fused weight converter: all weights fp32 -> fp16 ----------------
__global__ void convW_all_kernel(const float* __restrict__ cv1w, const float* __restrict__ mcv1w,
                                 const float* __restrict__ mqkvw, const float* __restrict__ mcv2w,
                                 const float* __restrict__ cv2w,
                                 uint16_t* __restrict__ Whi)
{
    long e = (long)blockIdx.x * 256 + threadIdx.x;
    if (e >= W_TOTAL) return;
    const float* W; long rel; int K; int isConv = 0;
    if (e < W_CONV0)      { W = cv1w; rel = e; K = 512; }
    else if (e < W_QKV0)  { long r = e - W_CONV0; int i = r >= 589824; rel = r - (long)i * 589824;
                            W = mcv1w + (long)i * 589824; K = 2304; isConv = 1; }
    else if (e < W_CV2M0) { long r = e - W_QKV0; int i = r >= 196608; rel = r - (long)i * 196608;
                            W = mqkvw + (long)i * 196608; K = 256; }
    else if (e < W_FIN)   { long r = e - W_CV2M0; int i = r >= 65536; rel = r - (long)i * 65536;
                            W = mcv2w + (long)i * 65536; K = 256; }
    else                  { W = cv2w; rel = e - W_FIN; K = 1024; }
    long m = rel / K, k = rel % K;
    float v;
    if (isConv) { int off = (int)(k >> 8), ci = (int)(k & 255); v = W[m * 2304 + ci * 9 + off]; }
    else v = W[rel];
    Whi[e] = __half_as_ushort(__float2half(v));
}

// ---------------- activation transposer: [b][K][HW] (T) -> fp16 [b][n][K] ----------------
template <typename T>
__global__ void convB_kernel(const T* __restrict__ In, long inStride, int K,
                             uint16_t* __restrict__ Bhi)
{
    __shared__ float t[32][33];
    int n0 = blockIdx.x * 32, k0 = blockIdx.y * 32, b = blockIdx.z;
    int tx = threadIdx.x, ty = threadIdx.y;
    const T* in = In + (long)b * inStride;
#pragma unroll
    for (int yy = 0; yy < 32; yy += 8)
        t[yy + ty][tx] = (float)in[(long)(k0 + yy + ty) * HW + n0 + tx];
    __syncthreads();
#pragma unroll
    for (int yy = 0; yy < 32; yy += 8) {
        int n = n0 + yy + ty, k = k0 + tx;
        float v = t[tx][yy + ty];
        long o = ((long)b * 1024 + n) * K + k;
        Bhi[o] = __half_as_ushort(__float2half(v));
    }
}

// ---------------- warp-MMA GEMM (N-tile 128): fp16, K-chunk 64, 2-stage ----------------
#define MG_STAGE 32768
#define MG_SMEM  65536

__device__ __forceinline__ void mg_load(uint32_t smb, int tid,
    const uint4* __restrict__ wHi, const uint4* __restrict__ bHi,
    int m0, int n0, int K16, int c, uint32_t stOff)
{
    uint32_t sb = smb + stOff;
#pragma unroll
    for (int l = 0; l < 4; l++) {
        int e = tid + l * 256;
        int r = e >> 3, j = e & 7;
        uint32_t off = SWZ128((uint32_t)(r * 128 + j * 16));
        cpa16(sb + off,         wHi + (long)(m0 + r) * K16 + c * 8 + j);
        cpa16(sb + 16384 + off, bHi + (long)(n0 + r) * K16 + c * 8 + j);
    }
}

extern __shared__ char mg_smem[];

__global__ void __launch_bounds__(256, 2) mgemm_kernel(
    const uint16_t* __restrict__ Bhi,
    const uint16_t* __restrict__ Whi,
    int K,
    float* __restrict__ Out, uint16_t* __restrict__ OutH, long outStride,
    const float* __restrict__ scale, const float* __restrict__ bias,
    const float* __restrict__ Res, long resStride,
    int doSilu)
{
    int b = blockIdx.z, m0 = blockIdx.y * 128, n0 = blockIdx.x * 128;
    int tid = threadIdx.x, wid = tid >> 5, lane = tid & 31;
    int warp_m = wid & 1, warp_n = wid >> 1;
    uint32_t smb = smem_u32(mg_smem);

    int K16 = K >> 3;
    const uint4* wHi = (const uint4*)Whi;
    const uint4* bHi = (const uint4*)(Bhi + (long)b * 1024 * K);

    float acc[4][4][4];
#pragma unroll
    for (int i = 0; i < 4; i++)
#pragma unroll
        for (int j = 0; j < 4; j++)
#pragma unroll
            for (int r = 0; r < 4; r++) acc[i][j][r] = 0.f;

    int nChunks = K >> 6;
    mg_load(smb, tid, wHi, bHi, m0, n0, K16, 0, 0);
    CPA_COMMIT();

    int aRowL = warp_m * 64 + (lane & 7) + (lane & 8);
    int aColL = ((lane >> 4) & 1) * 16;
    int bRowX4 = warp_n * 32 + (lane >> 4) * 8 + (lane & 7);
    uint32_t bColX4 = (uint32_t)(((lane >> 3) & 1) * 16);

    for (int c = 0; c < nChunks; c++) {
        int s = c & 1;
        CPA_WAIT0();
        __syncthreads();
        if (c + 1 < nChunks) {
            mg_load(smb, tid, wHi, bHi, m0, n0, K16, c + 1, (uint32_t)((s ^ 1) * MG_STAGE));
            CPA_COMMIT();
        }

        uint32_t base = smb + (uint32_t)(s * MG_STAGE);
#pragma unroll
        for (int ks = 0; ks < 4; ks++) {
            uint32_t ah[4][4], bh4[2][4];
#pragma unroll
            for (int mt = 0; mt < 4; mt++)
                ldsm_x4(ah[mt], base + SWZ128((uint32_t)((aRowL + mt * 16) * 128 + aColL + ks * 32)));
#pragma unroll
            for (int p = 0; p < 2; p++)
                ldsm_x4(bh4[p], base + 16384 + SWZ128((uint32_t)((bRowX4 + p * 16) * 128 + bColX4 + ks * 32)));
#pragma unroll
            for (int mt = 0; mt < 4; mt++)
#pragma unroll
                for (int p = 0; p < 2; p++) {
                    mma16816f(acc[mt][2 * p],     ah[mt], &bh4[p][0]);
                    mma16816f(acc[mt][2 * p + 1], ah[mt], &bh4[p][2]);
                }
        }
    }

#pragma unroll
    for (int mt = 0; mt < 4; mt++) {
        int mb = m0 + warp_m * 64 + mt * 16 + (lane >> 2);
#pragma unroll
        for (int h2 = 0; h2 < 2; h2++) {
            int m = mb + h2 * 8;
            float s = 1.f, bb = 0.f;
            if (scale) { s = scale[m]; bb = bias[m]; }
            long rowOff = (long)b * outStride + (long)m * HW;
            long resOff = Res ? ((long)b * resStride + (long)m * HW) : 0;
#pragma unroll
            for (int nt = 0; nt < 4; nt++) {
                int n = n0 + warp_n * 32 + nt * 8 + (lane & 3) * 2;
                float v0 = acc[mt][nt][h2 * 2 + 0] * s + bb;
                float v1 = acc[mt][nt][h2 * 2 + 1] * s + bb;
                if (doSilu) { v0 = silu_f(v0); v1 = silu_f(v1); }
                if (Res) {
                    float2 r2 = *(const float2*)&Res[resOff + n];
                    v0 += r2.x; v1 += r2.y;
                }
                if (Out) *(float2*)&Out[rowOff + n] = make_float2(v0, v1);
                if (OutH) {
                    __half2 hv = __floats2half2_rn(v0, v1);
                    *(__half2*)&OutH[rowOff + n] = hv;
                }
            }
        }
    }
}

// ---------------- warp-MMA GEMM (N-tile 64): fp16, K-chunk 64, 2-stage ----------------
#define MG64_STAGE 24576
#define MG64_SMEM  49152

__device__ __forceinline__ void mg64_load(uint32_t smb, int tid,
    const uint4* __restrict__ wHi, const uint4* __restrict__ bHi,
    int m0, int n0, int K16, int c, uint32_t stOff)
{
    uint32_t sb = smb + stOff;
#pragma unroll
    for (int l = 0; l < 4; l++) {
        int e = tid + l * 256;
        int r = e >> 3, j = e & 7;
        uint32_t off = SWZ128((uint32_t)(r * 128 + j * 16));
        cpa16(sb + off, wHi + (long)(m0 + r) * K16 + c * 8 + j);
    }
#pragma unroll
    for (int l = 0; l < 2; l++) {
        int e = tid + l * 256;
        int r = e >> 3, j = e & 7;
        uint32_t off = SWZ128((uint32_t)(r * 128 + j * 16));
        cpa16(sb + 16384 + off, bHi + (long)(n0 + r) * K16 + c * 8 + j);
    }
}

// implicit 3x3 conv B loader: B is yi in fp16 [n][256]; chunk c (64 wide) -> tap (c>>2), quarter (c&3)
__device__ __forceinline__ void mgc_load(uint32_t smb, int tid,
    const uint4* __restrict__ wHi, const uint4* __restrict__ bHi,
    int m0, int n0, int K16, int c, uint32_t stOff)
{
    uint32_t sb = smb + stOff;
#pragma unroll
    for (int l = 0; l < 4; l++) {
        int e = tid + l * 256;
        int r = e >> 3, j = e & 7;
        uint32_t off = SWZ128((uint32_t)(r * 128 + j * 16));
        cpa16(sb + off, wHi + (long)(m0 + r) * K16 + c * 8 + j);
    }
    int tap = c >> 2, q = c & 3;
    int dy = tap / 3 - 1, dx = tap % 3 - 1;
#pragma unroll
    for (int l = 0; l < 2; l++) {
        int e = tid + l * 256;
        int r = e >> 3, j = e & 7;
        int pix = n0 + r;
        int y = (pix >> 5) + dy, x = (pix & 31) + dx;
        bool ok = ((unsigned)y < 32u) && ((unsigned)x < 32u);
        int ps = ok ? (y * 32 + x) : 0;
        int sz = ok ? 16 : 0;
        uint32_t off = SWZ128((uint32_t)(r * 128 + j * 16));
        cpa16z(sb + 16384 + off, bHi + (long)ps * 32 + q * 8 + j, sz);
    }
}

template <int CONV>
__global__ void __launch_bounds__(256, 2) mgemm64_kernel_t(
    const uint16_t* __restrict__ Bhi,
    const uint16_t* __restrict__ Whi,
    int K, int bK,
    float* __restrict__ Out, uint16_t* __restrict__ OutH, long outStride,
    uint16_t* __restrict__ OutB,
    const float* __restrict__ scale, const float* __restrict__ bias,
    const float* __restrict__ Res, long resStride,
    int doSilu)
{
    int b = blockIdx.z, m0 = blockIdx.y * 128, n0 = blockIdx.x * 64;
    int tid = threadIdx.x, wid = tid >> 5, lane = tid & 31;
    int warp_m = wid & 3, warp_n = wid >> 2;
    uint32_t smb = smem_u32(mg_smem);

    int K16 = K >> 3;
    const uint4* wHi = (const uint4*)Whi;
    const uint4* bHi = (const uint4*)(Bhi + (long)b * 1024 * bK);

    float acc[2][4][4];
#pragma unroll
    for (int i = 0; i < 2; i++)
#pragma unroll
        for (int j = 0; j < 4; j++)
#pragma unroll
            for (int r = 0; r < 4; r++) acc[i][j][r] = 0.f;

    int nChunks = K >> 6;
    if (CONV) mgc_load(smb, tid, wHi, bHi, m0, n0, K16, 0, 0);
    else      mg64_load(smb, tid, wHi, bHi, m0, n0, K16, 0, 0);
    CPA_COMMIT();

    int aRowL = warp_m * 32 + (lane & 7) + (lane & 8);
    int aColL = ((lane >> 4) & 1) * 16;
    int bRowX4 = warp_n * 32 + (lane >> 4) * 8 + (lane & 7);
    uint32_t bColX4 = (uint32_t)(((lane >> 3) & 1) * 16);

    for (int c = 0; c < nChunks; c++) {
        int s = c & 1;
        CPA_WAIT0();
        __syncthreads();
        if (c + 1 < nChunks) {
            if (CONV) mgc_load(smb, tid, wHi, bHi, m0, n0, K16, c + 1, (uint32_t)((s ^ 1) * MG64_STAGE));
            else      mg64_load(smb, tid, wHi, bHi, m0, n0, K16, c + 1, (uint32_t)((s ^ 1) * MG64_STAGE));
            CPA_COMMIT();
        }

        uint32_t base = smb + (uint32_t)(s * MG64_STAGE);
#pragma unroll
        for (int ks = 0; ks < 4; ks++) {
            uint32_t ah[2][4], bh4[2][4];
#pragma unroll
            for (int mt = 0; mt < 2; mt++)
                ldsm_x4(ah[mt], base + SWZ128((uint32_t)((aRowL + mt * 16) * 128 + aColL + ks * 32)));
#pragma unroll
            for (int p = 0; p < 2; p++)
                ldsm_x4(bh4[p], base + 16384 + SWZ128((uint32_t)((bRowX4 + p * 16) * 128 + bColX4 + ks * 32)));
#pragma unroll
            for (int mt = 0; mt < 2; mt++)
#pragma unroll
                for (int p = 0; p < 2; p++) {
                    mma16816f(acc[mt][2 * p],     ah[mt], &bh4[p][0]);
                    mma16816f(acc[mt][2 * p + 1], ah[mt], &bh4[p][2]);
                }
        }
    }

    float* stage = (float*)mg_smem;   // [64][132] when OutB (33 KB < 48 KB)
    if (OutB) __syncthreads();

#pragma unroll
    for (int mt = 0; mt < 2; mt++) {
        int mlB = warp_m * 32 + mt * 16 + (lane >> 2);
#pragma unroll
        for (int h2 = 0; h2 < 2; h2++) {
            int ml = mlB + h2 * 8;
            int m = m0 + ml;
            float s = 1.f, bb = 0.f;
            if (scale) { s = scale[m]; bb = bias[m]; }
            long rowOff = (long)b * outStride + (long)m * HW;
            long resOff = Res ? ((long)b * resStride + (long)m * HW) : 0;
#pragma unroll
            for (int nt = 0; nt < 4; nt++) {
                int nl = warp_n * 32 + nt * 8 + (lane & 3) * 2;
                int n = n0 + nl;
                float v0 = acc[mt][nt][h2 * 2 + 0] * s + bb;
                float v1 = acc[mt][nt][h2 * 2 + 1] * s + bb;
                if (doSilu) { v0 = silu_f(v0); v1 = silu_f(v1); }
                if (Res) {
                    float2 r2 = *(const float2*)&Res[resOff + n];
                    v0 += r2.x; v1 += r2.y;
                }
                if (Out) *(float2*)&Out[rowOff + n] = make_float2(v0, v1);
                if (OutH) {
                    __half2 hv = __floats2half2_rn(v0, v1);
                    *(__half2*)&OutH[rowOff + n] = hv;
                }
                if (OutB) {
                    stage[nl * 132 + ml] = v0;
                    stage[(nl + 1) * 132 + ml] = v1;
                }
            }
        }
    }

    if (OutB) {
        __syncthreads();
        for (int e = tid; e < 4096; e += 256) {
            int row = e >> 6, c2 = e & 63;
            float v0 = stage[row * 132 + c2 * 2];
            float v1 = stage[row * 132 + c2 * 2 + 1];
            __half2 hv = __floats2half2_rn(v0, v1);
            *(__half2*)&OutB[((long)b * 1024 + n0 + row) * 256 + m0 + c2 * 2] = hv;
        }
    }
}

// ---------------- attention converter: qkv fp16 -> Qhi/Qlo (fp16 split-2), K(+relpos), V fp16 ----------------
__global__ void convAttn_kernel(const uint16_t* __restrict__ QKVH,
                                const float* __restrict__ RW, const float* __restrict__ RH,
                                uint16_t* __restrict__ Hi, uint16_t* __restrict__ QLo)
{
    __shared__ float tq[32][33], tk[32][33];
    int it = blockIdx.x, dt = blockIdx.y, bh = blockIdx.z;
    int b = bh >> 2, hh = bh & 3;
    int tx = threadIdx.x, ty = threadIdx.y;
    const __half* base = (const __half*)QKVH + (long)b * 768 * HW;
#pragma unroll
    for (int l = 0; l < 4; l++) {
        int d = dt * 32 + ty + l * 8;
        int ch = hh * 64 + d;
        float qv = __half2float(base[(long)ch * HW + it * 32 + tx]) * 0.125f;
        float kv = __half2float(base[(long)(256 + ch) * HW + it * 32 + tx]) + RW[ch * 32 + tx] + RH[ch * 32 + it];
        float vv = __half2float(base[(long)(512 + ch) * HW + it * 32 + tx]);
        tq[ty + l * 8][tx] = qv;
        tk[ty + l * 8][tx] = kv;
        long vo = V_OFF + ((long)bh * 64 + d) * 1024 + it * 32 + tx;
        Hi[vo] = __half_as_ushort(__float2half(vv));
    }
    __syncthreads();
#pragma unroll
    for (int l = 0; l < 4; l++) {
        int i = it * 32 + ty + l * 8;
        int d = dt * 32 + tx;
        float qv = tq[tx][ty + l * 8];
        float kv = tk[tx][ty + l * 8];
        long qo = ((long)bh * 1024 + i) * 64 + d;
        __half qh = __float2half(qv);
        Hi[QT_OFF + qo] = __half_as_ushort(qh);
        QLo[qo] = __half_as_ushort(__float2half(qv - __half2float(qh)));
        Hi[KT_OFF + qo] = __half_as_ushort(__float2half(kv));
    }
}

// ---------------- MMA flash attention (fp16: Q split-2, K/V plain), emits B-layout fp16 ----------------
// smem: stage s at s*32768: K 0..16KB, V 16..32KB. Q at 65536: Qh, Ql(+16384). Total 98304.
#define AT_SMEM 98304

__device__ __forceinline__ void kv_load(uint32_t smb, int tid,
    const uint16_t* __restrict__ kT, const uint16_t* __restrict__ vH,
    int bh, int t, uint32_t stOff)
{
    uint32_t kb = smb + stOff;
    const uint4* k4 = (const uint4*)(kT + ((long)bh * 1024 + t * 128) * 64);
    int r = tid >> 1, j0 = (tid & 1) * 4;
#pragma unroll
    for (int j = 0; j < 4; j++) {
        uint32_t off = SWZ128((uint32_t)(r * 128 + (j0 + j) * 16));
        cpa16(kb + off, k4 + (long)r * 8 + j0 + j);
    }
    const uint4* v4 = (const uint4*)(vH + (long)bh * 65536 + t * 128);
    int d = tid >> 2, jc0 = (tid & 3) * 4;
#pragma unroll
    for (int j = 0; j < 4; j++) {
        int jc = jc0 + j;
        uint32_t off = (uint32_t)((jc >> 3) * 8192) + SWZ128((uint32_t)(d * 128 + (jc & 7) * 16));
        cpa16(kb + 16384 + off, v4 + (long)d * 128 + jc);
    }
}

extern __shared__ char at_smem[];

__global__ void __launch_bounds__(256) attn_mma_kernel(
    const uint16_t* __restrict__ Hi, const uint16_t* __restrict__ QLo,
    uint16_t* __restrict__ OutB)
{
    int qt = blockIdx.x, h = blockIdx.y, b = blockIdx.z;
    int bh = b * 4 + h;
    int tid = threadIdx.x, wid = tid >> 5, lane = tid & 31, li = lane & 15;
    uint32_t smb = smem_u32(at_smem);

    const uint16_t* qTh = Hi + QT_OFF;
    const uint16_t* kT  = Hi + KT_OFF;
    const uint16_t* vH  = Hi + V_OFF;

    {
        const uint4* qh4 = (const uint4*)(qTh + ((long)bh * 1024 + qt * 128) * 64);
        const uint4* ql4 = (const uint4*)(QLo + ((long)bh * 1024 + qt * 128) * 64);
        int r = tid >> 1, j0 = (tid & 1) * 4;
        uint32_t qb = smb + 65536;
#pragma unroll
        for (int j = 0; j < 4; j++) {
            uint32_t off = SWZ128((uint32_t)(r * 128 + (j0 + j) * 16));
            cpa16(qb + off, qh4 + (long)r * 8 + j0 + j);
            cpa16(qb + 16384 + off, ql4 + (long)r * 8 + j0 + j);
        }
    }
    CPA_COMMIT();
    kv_load(smb, tid, kT, vH, bh, 0, 0);
    CPA_COMMIT();
    CPA_WAIT1();
    __syncthreads();

    uint32_t qfh[4][4], qfl[4][4];
    {
        int aRow = wid * 16 + (lane & 7) + (lane & 8);
        int aCol = ((lane >> 4) & 1) * 16;
#pragma unroll
        for (int ks = 0; ks < 4; ks++) {
            uint32_t off = SWZ128((uint32_t)(aRow * 128 + aCol + ks * 32));
            ldsm_x4(qfh[ks], smb + 65536 + off);
            ldsm_x4(qfl[ks], smb + 65536 + 16384 + off);
        }
    }

    float oacc[8][4];
#pragma unroll
    for (int i = 0; i < 8; i++)
#pragma unroll
        for (int j = 0; j < 4; j++) oacc[i][j] = 0.f;
    float m0 = -1e30f, m1 = -1e30f, l0 = 0.f, l1 = 0.f;

    int sRowX4 = (lane >> 4) * 8 + (lane & 7);
    uint32_t sColX4 = (uint32_t)(((lane >> 3) & 1) * 16);

    for (int t = 0; t < 8; t++) {
        int s = t & 1;
        if (t < 7) {
            kv_load(smb, tid, kT, vH, bh, t + 1, (uint32_t)((s ^ 1) * 32768));
            CPA_COMMIT();
            CPA_WAIT1();
        } else {
            CPA_WAIT0();
        }
        __syncthreads();

        uint32_t kb = smb + s * 32768;
        float sacc[16][4];
#pragma unroll
        for (int i = 0; i < 16; i++)
#pragma unroll
            for (int j = 0; j < 4; j++) sacc[i][j] = 0.f;

#pragma unroll
        for (int p = 0; p < 8; p++) {
            int rowB = p * 16 + sRowX4;
#pragma unroll
            for (int ks = 0; ks < 4; ks++) {
                uint32_t off = SWZ128((uint32_t)(rowB * 128 + sColX4 + ks * 32));
                uint32_t kh4[4];
                ldsm_x4(kh4, kb + off);
                mma16816f(sacc[2 * p],     qfh[ks], &kh4[0]);
                mma16816f(sacc[2 * p + 1], qfh[ks], &kh4[2]);
                mma16816f(sacc[2 * p],     qfl[ks], &kh4[0]);
                mma16816f(sacc[2 * p + 1], qfl[ks], &kh4[2]);
            }
        }

        float mx0 = m0, mx1 = m1;
#pragma unroll
        for (int nt = 0; nt < 16; nt++) {
            mx0 = fmaxf(mx0, fmaxf(sacc[nt][0], sacc[nt][1]));
            mx1 = fmaxf(mx1, fmaxf(sacc[nt][2], sacc[nt][3]));
        }
        mx0 = fmaxf(mx0, __shfl_xor_sync(0xffffffffu, mx0, 1));
        mx0 = fmaxf(mx0, __shfl_xor_sync(0xffffffffu, mx0, 2));
        mx1 = fmaxf(mx1, __shfl_xor_sync(0xffffffffu, mx1, 1));
        mx1 = fmaxf(mx1, __shfl_xor_sync(0xffffffffu, mx1, 2));
        float a0 = __expf(m0 - mx0), a1 = __expf(m1 - mx1);
        m0 = mx0; m1 = mx1;

        float ls0 = 0.f, ls1 = 0.f;
        uint32_t pah[8][4], pal[8][4];
#pragma unroll
        for (int kj = 0; kj < 8; kj++) {
            float p00 = __expf(sacc[2 * kj][0] - m0);
            float p01 = __expf(sacc[2 * kj][1] - m0);
            float p02 = __expf(sacc[2 * kj][2] - m1);
            float p03 = __expf(sacc[2 * kj][3] - m1);
            float p10 = __expf(sacc[2 * kj + 1][0] - m0);
            float p11 = __expf(sacc[2 * kj + 1][1] - m0);
            float p12 = __expf(sacc[2 * kj + 1][2] - m1);
            float p13 = __expf(sacc[2 * kj + 1][3] - m1);
            ls0 += p00 + p01 + p10 + p11;
            ls1 += p02 + p03 + p12 + p13;
            pah[kj][0] = packh(p00, p01);
            pah[kj][1] = packh(p02, p03);
            pah[kj][2] = packh(p10, p11);
            pah[kj][3] = packh(p12, p13);
            float q00 = p00 - __half2float(__float2half(p00));
            float q01 = p01 - __half2float(__float2half(p01));
            float q02 = p02 - __half2float(__float2half(p02));
            float q03 = p03 - __half2float(__float2half(p03));
            float q10 = p10 - __half2float(__float2half(p10));
            float q11 = p11 - __half2float(__float2half(p11));
            float q12 = p12 - __half2float(__float2half(p12));
            float q13 = p13 - __half2float(__float2half(p13));
            pal[kj][0] = packh(q00, q01);
            pal[kj][1] = packh(q02, q03);
            pal[kj][2] = packh(q10, q11);
            pal[kj][3] = packh(q12, q13);
        }
        ls0 += __shfl_xor_sync(0xffffffffu, ls0, 1);
        ls0 += __shfl_xor_sync(0xffffffffu, ls0, 2);
        ls1 += __shfl_xor_sync(0xffffffffu, ls1, 1);
        ls1 += __shfl_xor_sync(0xffffffffu, ls1, 2);
        l0 = l0 * a0 + ls0;
        l1 = l1 * a1 + ls1;
#pragma unroll
        for (int dt = 0; dt < 8; dt++) {
            oacc[dt][0] *= a0; oacc[dt][1] *= a0;
            oacc[dt][2] *= a1; oacc[dt][3] *= a1;
        }

#pragma unroll
        for (int dt = 0; dt < 8; dt++) {
            int rowV = dt * 8 + (li & 7);
#pragma unroll
            for (int kj = 0; kj < 8; kj++) {
                uint32_t off = (uint32_t)((kj >> 2) * 8192) +
                               SWZ128((uint32_t)(rowV * 128 + (li >> 3) * 16 + (kj & 3) * 32));
                uint32_t vh2[2];
                ldsm_x2(vh2, kb + 16384 + off);
                mma16816f(oacc[dt], pah[kj], vh2);
                mma16816f(oacc[dt], pal[kj], vh2);
            }
        }
        __syncthreads();
    }

    float i0 = 1.f / l0, i1 = 1.f / l1;
    float* stg = (float*)at_smem;   // [128][66]
    int r0 = wid * 16 + (lane >> 2);
#pragma unroll
    for (int dt = 0; dt < 8; dt++) {
        int d = dt * 8 + (lane & 3) * 2;
        stg[r0 * 66 + d]           = oacc[dt][0] * i0;
        stg[r0 * 66 + d + 1]       = oacc[dt][1] * i0;
        stg[(r0 + 8) * 66 + d]     = oacc[dt][2] * i1;
        stg[(r0 + 8) * 66 + d + 1] = oacc[dt][3] * i1;
    }
    __syncthreads();
    // emit B-layout fp16: [n = global token][k = 256 channels]
    for (int e = tid; e < 4096; e += 256) {
        int i = e >> 5, dp = (e & 31) * 2;
        __half2 hv = __floats2half2_rn(stg[i * 66 + dp], stg[i * 66 + dp + 1]);
        *(__half2*)&OutB[((long)b * 1024 + qt * 128 + i) * 256 + h * 64 + dp] = hv;
    }
}

// ---------------- launch ----------------
extern "C" void kernel_launch(void* const* d_in, const int* in_sizes, int n_in,
                              void* d_out, int out_size)
{
    const float* x      = (const float*)d_in[0];
    const float* cv1_w  = (const float*)d_in[1];
    const float* cv1_bn = (const float*)d_in[2];
    const float* cv2_w  = (const float*)d_in[3];
    const float* cv2_bn = (const float*)d_in[4];
    const float* mcv1w  = (const float*)d_in[5];
    const float* mcv1bn = (const float*)d_in[6];
    const float* mqkvw  = (const float*)d_in[7];
    const float* mrw    = (const float*)d_in[8];
    const float* mrh    = (const float*)d_in[9];
    const float* mcv2w  = (const float*)d_in[10];
    const float* mcv2bn = (const float*)d_in[11];
    float* out = (float*)d_out;

    float *cat, *scl, *bia;
    uint16_t *catH, *qkvH, *whi, *bhi, *blo;
    cudaGetSymbolAddress((void**)&cat,   g_cat);
    cudaGetSymbolAddress((void**)&catH,  g_catH);
    cudaGetSymbolAddress((void**)&qkvH,  g_qkvH);
    cudaGetSymbolAddress((void**)&scl,   g_scale);
    cudaGetSymbolAddress((void**)&bia,   g_bias);
    cudaGetSymbolAddress((void**)&whi,   g_Whi);
    cudaGetSymbolAddress((void**)&bhi,   g_Bhi);
    cudaGetSymbolAddress((void**)&blo,   g_Blo);

    cudaFuncSetAttribute(mgemm_kernel, cudaFuncAttributeMaxDynamicSharedMemorySize, MG_SMEM);
    cudaFuncSetAttribute(mgemm64_kernel_t<0>, cudaFuncAttributeMaxDynamicSharedMemorySize, MG64_SMEM);
    cudaFuncSetAttribute(mgemm64_kernel_t<1>, cudaFuncAttributeMaxDynamicSharedMemorySize, MG64_SMEM);
    cudaFuncSetAttribute(attn_mma_kernel, cudaFuncAttributeMaxDynamicSharedMemorySize, AT_SMEM);

    fold_bn_kernel<<<8, 256>>>(cv1_bn, cv2_bn, mcv1bn, mcv2bn);
    convW_all_kernel<<<(W_TOTAL + 255) / 256, 256>>>(cv1_w, mcv1w, mqkvw, mcv2w, cv2_w, whi);

    // ---- cv1: 512 -> 512, BN+SiLU -> fp32 cat[0:512) + fp16 catH[0:512) ----
    convB_kernel<float><<<dim3(32, 16, 8), dim3(32, 8)>>>(x, (long)512 * HW, 512, bhi + B0_OFF);
    mgemm_kernel<<<dim3(8, 4, 8), 256, MG_SMEM>>>(
        bhi + B0_OFF, whi + W_CV1, 512, cat, catH, (long)1024 * HW,
        scl + 0, bia + 0, nullptr, 0, 1);

    for (int i = 0; i < 2; i++) {
        long yin  = (long)(i == 0 ? 256 : 512) * HW;
        long yout = (long)(512 + i * 256) * HW;
        long wConv = i ? W_CONV1 : W_CONV0;
        long wQkv  = i ? W_QKV1  : W_QKV0;
        long wCv2  = i ? W_CV2M1 : W_CV2M0;

        // z = cbs(yi, 3x3) as IMPLICIT GEMM; emits fp16 B-layout ZB directly
        convB_kernel<__half><<<dim3(32, 8, 8), dim3(32, 8)>>>(
            (const __half*)(catH + yin), (long)1024 * HW, 256, bhi + B0_OFF);
        mgemm64_kernel_t<1><<<dim3(16, 2, 8), 256, MG64_SMEM>>>(
            bhi + B0_OFF, whi + wConv, 2304, 256,
            nullptr, nullptr, 0, bhi + ZB_OFF,
            scl + 1024 + i * 256, bia + 1024 + i * 256, nullptr, 0, 1);

        // qkv = conv1x1(z), 256 -> 768 (reads ZB directly); output fp16 qkvH
        mgemm_kernel<<<dim3(8, 6, 8), 256, MG_SMEM>>>(
            bhi + ZB_OFF, whi + wQkv, 256, nullptr, qkvH, (long)768 * HW,
            nullptr, nullptr, nullptr, 0, 0);

        // attention operand conversion (fp16) + MMA flash attention -> fp16 B-layout ATB
        convAttn_kernel<<<dim3(32, 2, 32), dim3(32, 8)>>>(
            qkvH, mrw + (long)i * 8192, mrh + (long)i * 8192, bhi, blo);
        attn_mma_kernel<<<dim3(8, 4, 8), 256, AT_SMEM>>>(bhi, blo, bhi + ATB_OFF);

        // y_{i+2} = yi + silu(bn(conv1x1(attn))) (reads ATB) -> fp32 cat + fp16 catH
        mgemm64_kernel_t<0><<<dim3(16, 2, 8), 256, MG64_SMEM>>>(
            bhi + ATB_OFF, whi + wCv2, 256, 256,
            cat + yout, catH + yout, (long)1024 * HW, nullptr,
            scl + 1536 + i * 256, bia + 1536 + i * 256, cat + yin, (long)1024 * HW, 1);
    }

    // ---- final: 1024 -> 512, BN+SiLU, fp32 out ----
    convB_kernel<__half><<<dim3(32, 32, 8), dim3(32, 8)>>>(
        (const __half*)catH, (long)1024 * HW, 1024, bhi + B0_OFF);
    mgemm_kernel<<<dim3(8, 4, 8), 256, MG_SMEM>>>(
        bhi + B0_OFF, whi + W_FIN, 1024, out, nullptr, (long)512 * HW,
        scl + 512, bia + 512, nullptr, 0, 1);
}

// round 16
// speedup vs baseline: 1.2246x; 1.0177x over previous
#include <cuda_runtime.h>
#include <cuda_fp16.h>
#include <cstdint>

#define HW 1024

// ---------------- scratch (__device__ globals: alloc-guard-safe) ----------------
__device__ float    g_cat  [8u * 1024u * HW];   // 32 MB fp32 (residual path)
__device__ uint16_t g_qkvH [8u * 768u  * HW];   // fp16 qkv
__device__ float g_scale[2048];
__device__ float g_bias [2048];
__device__ uint16_t g_Whi[2490368];
__device__ uint16_t g_Bhi[23068672];            // 44 MB arena
__device__ uint16_t g_Blo[2097152];             // Q-lo

// arena offsets (elements) inside g_Bhi
#define XB_OFF    0u         // x as B (K=512):       4,194,304
#define CATB_OFF  4194304u   // concat B [n][1024]:   8,388,608
#define ZB_OFF    12582912u  // conv out B [n][256]:  2,097,152
#define ATB_OFF   14680064u  // attn out B [n][256]:  2,097,152
#define QT_OFF    16777216u  // fp16 Q hi
#define KT_OFF    18874368u  // fp16 K (+relpos)
#define V_OFF     20971520u  // fp16 V

// weight arena offsets
#define W_CV1   0
#define W_CONV0 262144
#define W_CONV1 851968
#define W_QKV0  1441792
#define W_QKV1  1638400
#define W_CV2M0 1835008
#define W_CV2M1 1900544
#define W_FIN   1966080
#define W_TOTAL 2490368

__device__ __forceinline__ float silu_f(float v) { return v / (1.f + __expf(-v)); }

__device__ __forceinline__ uint32_t smem_u32(const void* p) {
    uint32_t a;
    asm("{ .reg .u64 t; cvta.to.shared.u64 t, %1; cvt.u32.u64 %0, t; }" : "=r"(a) : "l"(p));
    return a;
}
#define SWZ128(o) ((o) ^ (((o) >> 3) & 0x70))

__device__ __forceinline__ void ldsm_x4(uint32_t* r, uint32_t a) {
    asm volatile("ldmatrix.sync.aligned.m8n8.x4.shared.b16 {%0,%1,%2,%3}, [%4];"
        : "=r"(r[0]), "=r"(r[1]), "=r"(r[2]), "=r"(r[3]) : "r"(a));
}
__device__ __forceinline__ void ldsm_x2(uint32_t* r, uint32_t a) {
    asm volatile("ldmatrix.sync.aligned.m8n8.x2.shared.b16 {%0,%1}, [%2];"
        : "=r"(r[0]), "=r"(r[1]) : "r"(a));
}
__device__ __forceinline__ void mma16816f(float* d, const uint32_t* a, const uint32_t* b) {
    asm volatile("mma.sync.aligned.m16n8k16.row.col.f32.f16.f16.f32 "
        "{%0,%1,%2,%3}, {%4,%5,%6,%7}, {%8,%9}, {%0,%1,%2,%3};"
        : "+f"(d[0]), "+f"(d[1]), "+f"(d[2]), "+f"(d[3])
        : "r"(a[0]), "r"(a[1]), "r"(a[2]), "r"(a[3]), "r"(b[0]), "r"(b[1]));
}
__device__ __forceinline__ void cpa16(uint32_t d, const void* s) {
    asm volatile("cp.async.cg.shared.global [%0], [%1], 16;" :: "r"(d), "l"(s));
}
__device__ __forceinline__ void cpa16z(uint32_t d, const void* s, int sz) {
    asm volatile("cp.async.cg.shared.global [%0], [%1], 16, %2;" :: "r"(d), "l"(s), "r"(sz));
}
#define CPA_COMMIT() asm volatile("cp.async.commit_group;" ::: "memory")
#define CPA_WAIT1()  asm volatile("cp.async.wait_group 1;" ::: "memory")
#define CPA_WAIT0()  asm volatile("cp.async.wait_group 0;" ::: "memory")

__device__ __forceinline__ uint32_t packh(float lo, float hi) {
    __half2 h = __floats2half2_rn(lo, hi);
    return *(uint32_t*)&h;
}

// ---------------- BN fold ----------------
__global__ void fold_bn_kernel(const float* __restrict__ cv1, const float* __restrict__ cv2,
                               const float* __restrict__ mcv1, const float* __restrict__ mcv2)
{
    int c = blockIdx.x * 256 + threadIdx.x;
    if (c >= 2048) return;
    const float* p; int C, lc;
    if (c < 512)        { p = cv1;  C = 512; lc = c; }
    else if (c < 1024)  { p = cv2;  C = 512; lc = c - 512; }
    else if (c < 1536)  { int i = (c - 1024) >> 8; p = mcv1 + i * 1024; C = 256; lc = (c - 1024) & 255; }
    else                { int i = (c - 1536) >> 8; p = mcv2 + i * 1024; C = 256; lc = (c - 1536) & 255; }
    float g = p[lc], b = p[C + lc], m = p[2 * C + lc], v = p[3 * C + lc];
    float s = g / sqrtf(v + 1e-3f);
    g_scale[c] = s;
    g_bias[c]  = b - m * s;
}

// ---------------- fused weight converter: all weights fp32 -> fp16 ----------------
__global__ void convW_all_kernel(const float* __restrict__ cv1w, const float* __restrict__ mcv1w,
                                 const float* __restrict__ mqkvw, const float* __restrict__ mcv2w,
                                 const float* __restrict__ cv2w,
                                 uint16_t* __restrict__ Whi)
{
    long e = (long)blockIdx.x * 256 + threadIdx.x;
    if (e >= W_TOTAL) return;
    const float* W; long rel; int K; int isConv = 0;
    if (e < W_CONV0)      { W = cv1w; rel = e; K = 512; }
    else if (e < W_QKV0)  { long r = e - W_CONV0; int i = r >= 589824; rel = r - (long)i * 589824;
                            W = mcv1w + (long)i * 589824; K = 2304; isConv = 1; }
    else if (e < W_CV2M0) { long r = e - W_QKV0; int i = r >= 196608; rel = r - (long)i * 196608;
                            W = mqkvw + (long)i * 196608; K = 256; }
    else if (e < W_FIN)   { long r = e - W_CV2M0; int i = r >= 65536; rel = r - (long)i * 65536;
                            W = mcv2w + (long)i * 65536; K = 256; }
    else                  { W = cv2w; rel = e - W_FIN; K = 1024; }
    long m = rel / K, k = rel % K;
    float v;
    if (isConv) { int off = (int)(k >> 8), ci = (int)(k & 255); v = W[m * 2304 + ci * 9 + off]; }
    else v = W[rel];
    Whi[e] = __half_as_ushort(__float2half(v));
}

// ---------------- activation transposer: [b][K][HW] fp32 -> fp16 [b][n][K] (x only) ----------------
__global__ void convB_kernel(const float* __restrict__ In, long inStride, int K,
                             uint16_t* __restrict__ Bhi)
{
    __shared__ float t[32][33];
    int n0 = blockIdx.x * 32, k0 = blockIdx.y * 32, b = blockIdx.z;
    int tx = threadIdx.x, ty = threadIdx.y;
    const float* in = In + (long)b * inStride;
#pragma unroll
    for (int yy = 0; yy < 32; yy += 8)
        t[yy + ty][tx] = in[(long)(k0 + yy + ty) * HW + n0 + tx];
    __syncthreads();
#pragma unroll
    for (int yy = 0; yy < 32; yy += 8) {
        int n = n0 + yy + ty, k = k0 + tx;
        float v = t[tx][yy + ty];
        long o = ((long)b * 1024 + n) * K + k;
        Bhi[o] = __half_as_ushort(__float2half(v));
    }
}

// ---------------- warp-MMA GEMM (N-tile 128): fp16, K-chunk 64, 2-stage ----------------
#define MG_STAGE 32768
#define MG_SMEM  65536

__device__ __forceinline__ void mg_load(uint32_t smb, int tid,
    const uint4* __restrict__ wHi, const uint4* __restrict__ bHi,
    int m0, int n0, int K16, int c, uint32_t stOff)
{
    uint32_t sb = smb + stOff;
#pragma unroll
    for (int l = 0; l < 4; l++) {
        int e = tid + l * 256;
        int r = e >> 3, j = e & 7;
        uint32_t off = SWZ128((uint32_t)(r * 128 + j * 16));
        cpa16(sb + off,         wHi + (long)(m0 + r) * K16 + c * 8 + j);
        cpa16(sb + 16384 + off, bHi + (long)(n0 + r) * K16 + c * 8 + j);
    }
}

extern __shared__ char mg_smem[];

__global__ void __launch_bounds__(256, 2) mgemm_kernel(
    const uint16_t* __restrict__ Bhi,
    const uint16_t* __restrict__ Whi,
    int K,
    float* __restrict__ Out, uint16_t* __restrict__ OutH, long outStride,
    uint16_t* __restrict__ OutB, int kOutB, int kBaseB,
    const float* __restrict__ scale, const float* __restrict__ bias,
    const float* __restrict__ Res, long resStride,
    int doSilu)
{
    int b = blockIdx.z, m0 = blockIdx.y * 128, n0 = blockIdx.x * 128;
    int tid = threadIdx.x, wid = tid >> 5, lane = tid & 31;
    int warp_m = wid & 1, warp_n = wid >> 1;
    uint32_t smb = smem_u32(mg_smem);

    int K16 = K >> 3;
    const uint4* wHi = (const uint4*)Whi;
    const uint4* bHi = (const uint4*)(Bhi + (long)b * 1024 * K);

    float acc[4][4][4];
#pragma unroll
    for (int i = 0; i < 4; i++)
#pragma unroll
        for (int j = 0; j < 4; j++)
#pragma unroll
            for (int r = 0; r < 4; r++) acc[i][j][r] = 0.f;

    int nChunks = K >> 6;
    mg_load(smb, tid, wHi, bHi, m0, n0, K16, 0, 0);
    CPA_COMMIT();

    int aRowL = warp_m * 64 + (lane & 7) + (lane & 8);
    int aColL = ((lane >> 4) & 1) * 16;
    int bRowX4 = warp_n * 32 + (lane >> 4) * 8 + (lane & 7);
    uint32_t bColX4 = (uint32_t)(((lane >> 3) & 1) * 16);

    for (int c = 0; c < nChunks; c++) {
        int s = c & 1;
        CPA_WAIT0();
        __syncthreads();
        if (c + 1 < nChunks) {
            mg_load(smb, tid, wHi, bHi, m0, n0, K16, c + 1, (uint32_t)((s ^ 1) * MG_STAGE));
            CPA_COMMIT();
        }

        uint32_t base = smb + (uint32_t)(s * MG_STAGE);
#pragma unroll
        for (int ks = 0; ks < 4; ks++) {
            uint32_t ah[4][4], bh4[2][4];
#pragma unroll
            for (int mt = 0; mt < 4; mt++)
                ldsm_x4(ah[mt], base + SWZ128((uint32_t)((aRowL + mt * 16) * 128 + aColL + ks * 32)));
#pragma unroll
            for (int p = 0; p < 2; p++)
                ldsm_x4(bh4[p], base + 16384 + SWZ128((uint32_t)((bRowX4 + p * 16) * 128 + bColX4 + ks * 32)));
#pragma unroll
            for (int mt = 0; mt < 4; mt++)
#pragma unroll
                for (int p = 0; p < 2; p++) {
                    mma16816f(acc[mt][2 * p],     ah[mt], &bh4[p][0]);
                    mma16816f(acc[mt][2 * p + 1], ah[mt], &bh4[p][2]);
                }
        }
    }

    // ---- postprocess acc in place ----
#pragma unroll
    for (int mt = 0; mt < 4; mt++) {
        int mb = m0 + warp_m * 64 + mt * 16 + (lane >> 2);
#pragma unroll
        for (int h2 = 0; h2 < 2; h2++) {
            int m = mb + h2 * 8;
            float s = 1.f, bb = 0.f;
            if (scale) { s = scale[m]; bb = bias[m]; }
            long resOff = Res ? ((long)b * resStride + (long)m * HW) : 0;
#pragma unroll
            for (int nt = 0; nt < 4; nt++) {
                int n = n0 + warp_n * 32 + nt * 8 + (lane & 3) * 2;
                float v0 = acc[mt][nt][h2 * 2 + 0] * s + bb;
                float v1 = acc[mt][nt][h2 * 2 + 1] * s + bb;
                if (doSilu) { v0 = silu_f(v0); v1 = silu_f(v1); }
                if (Res) {
                    float2 r2 = *(const float2*)&Res[resOff + n];
                    v0 += r2.x; v1 += r2.y;
                }
                acc[mt][nt][h2 * 2 + 0] = v0;
                acc[mt][nt][h2 * 2 + 1] = v1;
            }
        }
    }

    if (Out || OutH) {
#pragma unroll
        for (int mt = 0; mt < 4; mt++) {
            int mb = m0 + warp_m * 64 + mt * 16 + (lane >> 2);
#pragma unroll
            for (int h2 = 0; h2 < 2; h2++) {
                int m = mb + h2 * 8;
                long rowOff = (long)b * outStride + (long)m * HW;
#pragma unroll
                for (int nt = 0; nt < 4; nt++) {
                    int n = n0 + warp_n * 32 + nt * 8 + (lane & 3) * 2;
                    float v0 = acc[mt][nt][h2 * 2 + 0];
                    float v1 = acc[mt][nt][h2 * 2 + 1];
                    if (Out) *(float2*)&Out[rowOff + n] = make_float2(v0, v1);
                    if (OutH) {
                        __half2 hv = __floats2half2_rn(v0, v1);
                        *(__half2*)&OutH[rowOff + n] = hv;
                    }
                }
            }
        }
    }

    if (OutB) {
        float* stage = (float*)mg_smem;   // [64 n][132 m]
#pragma unroll
        for (int half = 0; half < 2; half++) {
            __syncthreads();
            if ((warp_n >> 1) == half) {
#pragma unroll
                for (int mt = 0; mt < 4; mt++) {
#pragma unroll
                    for (int h2 = 0; h2 < 2; h2++) {
                        int ml = warp_m * 64 + mt * 16 + (lane >> 2) + h2 * 8;
#pragma unroll
                        for (int nt = 0; nt < 4; nt++) {
                            int nl = warp_n * 32 + nt * 8 + (lane & 3) * 2 - half * 64;
                            stage[nl * 132 + ml]       = acc[mt][nt][h2 * 2 + 0];
                            stage[(nl + 1) * 132 + ml] = acc[mt][nt][h2 * 2 + 1];
                        }
                    }
                }
            }
            __syncthreads();
            for (int e = tid; e < 4096; e += 256) {
                int row = e >> 6, c2 = e & 63;
                __half2 hv = __floats2half2_rn(stage[row * 132 + c2 * 2],
                                               stage[row * 132 + c2 * 2 + 1]);
                *(__half2*)&OutB[((long)b * 1024 + n0 + half * 64 + row) * kOutB
                                 + kBaseB + m0 + c2 * 2] = hv;
            }
        }
    }
}

// ---------------- warp-MMA GEMM (N-tile 64): fp16, K-chunk 64, 2-stage ----------------
#define MG64_STAGE 24576
#define MG64_SMEM  49152

__device__ __forceinline__ void mg64_load(uint32_t smb, int tid,
    const uint4* __restrict__ wHi, const uint4* __restrict__ bHi,
    int m0, int n0, int K16, int c, uint32_t stOff)
{
    uint32_t sb = smb + stOff;
#pragma unroll
    for (int l = 0; l < 4; l++) {
        int e = tid + l * 256;
        int r = e >> 3, j = e & 7;
        uint32_t off = SWZ128((uint32_t)(r * 128 + j * 16));
        cpa16(sb + off, wHi + (long)(m0 + r) * K16 + c * 8 + j);
    }
#pragma unroll
    for (int l = 0; l < 2; l++) {
        int e = tid + l * 256;
        int r = e >> 3, j = e & 7;
        uint32_t off = SWZ128((uint32_t)(r * 128 + j * 16));
        cpa16(sb + 16384 + off, bHi + (long)(n0 + r) * K16 + c * 8 + j);
    }
}

// implicit 3x3 conv B loader: B rows have bK16 uint4 stride, data at colBase16;
// chunk c (64 wide) -> tap (c>>2), quarter (c&3)
__device__ __forceinline__ void mgc_load(uint32_t smb, int tid,
    const uint4* __restrict__ wHi, const uint4* __restrict__ bHi,
    int m0, int n0, int K16, int bK16, int colBase16, int c, uint32_t stOff)
{
    uint32_t sb = smb + stOff;
#pragma unroll
    for (int l = 0; l < 4; l++) {
        int e = tid + l * 256;
        int r = e >> 3, j = e & 7;
        uint32_t off = SWZ128((uint32_t)(r * 128 + j * 16));
        cpa16(sb + off, wHi + (long)(m0 + r) * K16 + c * 8 + j);
    }
    int tap = c >> 2, q = c & 3;
    int dy = tap / 3 - 1, dx = tap % 3 - 1;
#pragma unroll
    for (int l = 0; l < 2; l++) {
        int e = tid + l * 256;
        int r = e >> 3, j = e & 7;
        int pix = n0 + r;
        int y = (pix >> 5) + dy, x = (pix & 31) + dx;
        bool ok = ((unsigned)y < 32u) && ((unsigned)x < 32u);
        int ps = ok ? (y * 32 + x) : 0;
        int sz = ok ? 16 : 0;
        uint32_t off = SWZ128((uint32_t)(r * 128 + j * 16));
        cpa16z(sb + 16384 + off, bHi + (long)ps * bK16 + colBase16 + q * 8 + j, sz);
    }
}

template <int CONV>
__global__ void __launch_bounds__(256, 2) mgemm64_kernel_t(
    const uint16_t* __restrict__ Bhi,
    const uint16_t* __restrict__ Whi,
    int K, int bK, int colBase16,
    float* __restrict__ Out, long outStride,
    uint16_t* __restrict__ OutB, int kOutB, int kBaseB,
    const float* __restrict__ scale, const float* __restrict__ bias,
    const float* __restrict__ Res, long resStride,
    int doSilu)
{
    int b = blockIdx.z, m0 = blockIdx.y * 128, n0 = blockIdx.x * 64;
    int tid = threadIdx.x, wid = tid >> 5, lane = tid & 31;
    int warp_m = wid & 3, warp_n = wid >> 2;
    uint32_t smb = smem_u32(mg_smem);

    int K16 = K >> 3;
    int bK16 = bK >> 3;
    const uint4* wHi = (const uint4*)Whi;
    const uint4* bHi = (const uint4*)(Bhi + (long)b * 1024 * bK);

    float acc[2][4][4];
#pragma unroll
    for (int i = 0; i < 2; i++)
#pragma unroll
        for (int j = 0; j < 4; j++)
#pragma unroll
            for (int r = 0; r < 4; r++) acc[i][j][r] = 0.f;

    int nChunks = K >> 6;
    if (CONV) mgc_load(smb, tid, wHi, bHi, m0, n0, K16, bK16, colBase16, 0, 0);
    else      mg64_load(smb, tid, wHi, bHi, m0, n0, K16, 0, 0);
    CPA_COMMIT();

    int aRowL = warp_m * 32 + (lane & 7) + (lane & 8);
    int aColL = ((lane >> 4) & 1) * 16;
    int bRowX4 = warp_n * 32 + (lane >> 4) * 8 + (lane & 7);
    uint32_t bColX4 = (uint32_t)(((lane >> 3) & 1) * 16);

    for (int c = 0; c < nChunks; c++) {
        int s = c & 1;
        CPA_WAIT0();
        __syncthreads();
        if (c + 1 < nChunks) {
            if (CONV) mgc_load(smb, tid, wHi, bHi, m0, n0, K16, bK16, colBase16, c + 1, (uint32_t)((s ^ 1) * MG64_STAGE));
            else      mg64_load(smb, tid, wHi, bHi, m0, n0, K16, c + 1, (uint32_t)((s ^ 1) * MG64_STAGE));
            CPA_COMMIT();
        }

        uint32_t base = smb + (uint32_t)(s * MG64_STAGE);
#pragma unroll
        for (int ks = 0; ks < 4; ks++) {
            uint32_t ah[2][4], bh4[2][4];
#pragma unroll
            for (int mt = 0; mt < 2; mt++)
                ldsm_x4(ah[mt], base + SWZ128((uint32_t)((aRowL + mt * 16) * 128 + aColL + ks * 32)));
#pragma unroll
            for (int p = 0; p < 2; p++)
                ldsm_x4(bh4[p], base + 16384 + SWZ128((uint32_t)((bRowX4 + p * 16) * 128 + bColX4 + ks * 32)));
#pragma unroll
            for (int mt = 0; mt < 2; mt++)
#pragma unroll
                for (int p = 0; p < 2; p++) {
                    mma16816f(acc[mt][2 * p],     ah[mt], &bh4[p][0]);
                    mma16816f(acc[mt][2 * p + 1], ah[mt], &bh4[p][2]);
                }
        }
    }

    float* stage = (float*)mg_smem;   // [64 n][132 m] when OutB
    if (OutB) __syncthreads();

#pragma unroll
    for (int mt = 0; mt < 2; mt++) {
        int mlB = warp_m * 32 + mt * 16 + (lane >> 2);
#pragma unroll
        for (int h2 = 0; h2 < 2; h2++) {
            int ml = mlB + h2 * 8;
            int m = m0 + ml;
            float s = 1.f, bb = 0.f;
            if (scale) { s = scale[m]; bb = bias[m]; }
            long rowOff = (long)b * outStride + (long)m * HW;
            long resOff = Res ? ((long)b * resStride + (long)m * HW) : 0;
#pragma unroll
            for (int nt = 0; nt < 4; nt++) {
                int nl = warp_n * 32 + nt * 8 + (lane & 3) * 2;
                int n = n0 + nl;
                float v0 = acc[mt][nt][h2 * 2 + 0] * s + bb;
                float v1 = acc[mt][nt][h2 * 2 + 1] * s + bb;
                if (doSilu) { v0 = silu_f(v0); v1 = silu_f(v1); }
                if (Res) {
                    float2 r2 = *(const float2*)&Res[resOff + n];
                    v0 += r2.x; v1 += r2.y;
                }
                if (Out) *(float2*)&Out[rowOff + n] = make_float2(v0, v1);
                if (OutB) {
                    stage[nl * 132 + ml] = v0;
                    stage[(nl + 1) * 132 + ml] = v1;
                }
            }
        }
    }

    if (OutB) {
        __syncthreads();
        for (int e = tid; e < 4096; e += 256) {
            int row = e >> 6, c2 = e & 63;
            __half2 hv = __floats2half2_rn(stage[row * 132 + c2 * 2],
                                           stage[row * 132 + c2 * 2 + 1]);
            *(__half2*)&OutB[((long)b * 1024 + n0 + row) * kOutB + kBaseB + m0 + c2 * 2] = hv;
        }
    }
}

// ---------------- attention converter: qkv fp16 -> Qhi/Qlo (fp16 split-2), K(+relpos), V fp16 ----------------
__global__ void convAttn_kernel(const uint16_t* __restrict__ QKVH,
                                const float* __restrict__ RW, const float* __restrict__ RH,
                                uint16_t* __restrict__ Hi, uint16_t* __restrict__ QLo)
{
    __shared__ float tq[32][33], tk[32][33];
    int it = blockIdx.x, dt = blockIdx.y, bh = blockIdx.z;
    int b = bh >> 2, hh = bh & 3;
    int tx = threadIdx.x, ty = threadIdx.y;
    const __half* base = (const __half*)QKVH + (long)b * 768 * HW;
#pragma unroll
    for (int l = 0; l < 4; l++) {
        int d = dt * 32 + ty + l * 8;
        int ch = hh * 64 + d;
        float qv = __half2float(base[(long)ch * HW + it * 32 + tx]) * 0.125f;
        float kv = __half2float(base[(long)(256 + ch) * HW + it * 32 + tx]) + RW[ch * 32 + tx] + RH[ch * 32 + it];
        float vv = __half2float(base[(long)(512 + ch) * HW + it * 32 + tx]);
        tq[ty + l * 8][tx] = qv;
        tk[ty + l * 8][tx] = kv;
        long vo = V_OFF + ((long)bh * 64 + d) * 1024 + it * 32 + tx;
        Hi[vo] = __half_as_ushort(__float2half(vv));
    }
    __syncthreads();
#pragma unroll
    for (int l = 0; l < 4; l++) {
        int i = it * 32 + ty + l * 8;
        int d = dt * 32 + tx;
        float qv = tq[tx][ty + l * 8];
        float kv = tk[tx][ty + l * 8];
        long qo = ((long)bh * 1024 + i) * 64 + d;
        __half qh = __float2half(qv);
        Hi[QT_OFF + qo] = __half_as_ushort(qh);
        QLo[qo] = __half_as_ushort(__float2half(qv - __half2float(qh)));
        Hi[KT_OFF + qo] = __half_as_ushort(__float2half(kv));
    }
}

// ---------------- MMA flash attention (fp16: Q split-2, K/V plain), emits B-layout fp16 ----------------
#define AT_SMEM 98304

__device__ __forceinline__ void kv_load(uint32_t smb, int tid,
    const uint16_t* __restrict__ kT, const uint16_t* __restrict__ vH,
    int bh, int t, uint32_t stOff)
{
    uint32_t kb = smb + stOff;
    const uint4* k4 = (const uint4*)(kT + ((long)bh * 1024 + t * 128) * 64);
    int r = tid >> 1, j0 = (tid & 1) * 4;
#pragma unroll
    for (int j = 0; j < 4; j++) {
        uint32_t off = SWZ128((uint32_t)(r * 128 + (j0 + j) * 16));
        cpa16(kb + off, k4 + (long)r * 8 + j0 + j);
    }
    const uint4* v4 = (const uint4*)(vH + (long)bh * 65536 + t * 128);
    int d = tid >> 2, jc0 = (tid & 3) * 4;
#pragma unroll
    for (int j = 0; j < 4; j++) {
        int jc = jc0 + j;
        uint32_t off = (uint32_t)((jc >> 3) * 8192) + SWZ128((uint32_t)(d * 128 + (jc & 7) * 16));
        cpa16(kb + 16384 + off, v4 + (long)d * 128 + jc);
    }
}

extern __shared__ char at_smem[];

__global__ void __launch_bounds__(256) attn_mma_kernel(
    const uint16_t* __restrict__ Hi, const uint16_t* __restrict__ QLo,
    uint16_t* __restrict__ OutB)
{
    int qt = blockIdx.x, h = blockIdx.y, b = blockIdx.z;
    int bh = b * 4 + h;
    int tid = threadIdx.x, wid = tid >> 5, lane = tid & 31, li = lane & 15;
    uint32_t smb = smem_u32(at_smem);

    const uint16_t* qTh = Hi + QT_OFF;
    const uint16_t* kT  = Hi + KT_OFF;
    const uint16_t* vH  = Hi + V_OFF;

    {
        const uint4* qh4 = (const uint4*)(qTh + ((long)bh * 1024 + qt * 128) * 64);
        const uint4* ql4 = (const uint4*)(QLo + ((long)bh * 1024 + qt * 128) * 64);
        int r = tid >> 1, j0 = (tid & 1) * 4;
        uint32_t qb = smb + 65536;
#pragma unroll
        for (int j = 0; j < 4; j++) {
            uint32_t off = SWZ128((uint32_t)(r * 128 + (j0 + j) * 16));
            cpa16(qb + off, qh4 + (long)r * 8 + j0 + j);
            cpa16(qb + 16384 + off, ql4 + (long)r * 8 + j0 + j);
        }
    }
    CPA_COMMIT();
    kv_load(smb, tid, kT, vH, bh, 0, 0);
    CPA_COMMIT();
    CPA_WAIT1();
    __syncthreads();

    uint32_t qfh[4][4], qfl[4][4];
    {
        int aRow = wid * 16 + (lane & 7) + (lane & 8);
        int aCol = ((lane >> 4) & 1) * 16;
#pragma unroll
        for (int ks = 0; ks < 4; ks++) {
            uint32_t off = SWZ128((uint32_t)(aRow * 128 + aCol + ks * 32));
            ldsm_x4(qfh[ks], smb + 65536 + off);
            ldsm_x4(qfl[ks], smb + 65536 + 16384 + off);
        }
    }

    float oacc[8][4];
#pragma unroll
    for (int i = 0; i < 8; i++)
#pragma unroll
        for (int j = 0; j < 4; j++) oacc[i][j] = 0.f;
    float m0 = -1e30f, m1 = -1e30f, l0 = 0.f, l1 = 0.f;

    int sRowX4 = (lane >> 4) * 8 + (lane & 7);
    uint32_t sColX4 = (uint32_t)(((lane >> 3) & 1) * 16);

    for (int t = 0; t < 8; t++) {
        int s = t & 1;
        if (t < 7) {
            kv_load(smb, tid, kT, vH, bh, t + 1, (uint32_t)((s ^ 1) * 32768));
            CPA_COMMIT();
            CPA_WAIT1();
        } else {
            CPA_WAIT0();
        }
        __syncthreads();

        uint32_t kb = smb + s * 32768;
        float sacc[16][4];
#pragma unroll
        for (int i = 0; i < 16; i++)
#pragma unroll
            for (int j = 0; j < 4; j++) sacc[i][j] = 0.f;

#pragma unroll
        for (int p = 0; p < 8; p++) {
            int rowB = p * 16 + sRowX4;
#pragma unroll
            for (int ks = 0; ks < 4; ks++) {
                uint32_t off = SWZ128((uint32_t)(rowB * 128 + sColX4 + ks * 32));
                uint32_t kh4[4];
                ldsm_x4(kh4, kb + off);
                mma16816f(sacc[2 * p],     qfh[ks], &kh4[0]);
                mma16816f(sacc[2 * p + 1], qfh[ks], &kh4[2]);
                mma16816f(sacc[2 * p],     qfl[ks], &kh4[0]);
                mma16816f(sacc[2 * p + 1], qfl[ks], &kh4[2]);
            }
        }

        float mx0 = m0, mx1 = m1;
#pragma unroll
        for (int nt = 0; nt < 16; nt++) {
            mx0 = fmaxf(mx0, fmaxf(sacc[nt][0], sacc[nt][1]));
            mx1 = fmaxf(mx1, fmaxf(sacc[nt][2], sacc[nt][3]));
        }
        mx0 = fmaxf(mx0, __shfl_xor_sync(0xffffffffu, mx0, 1));
        mx0 = fmaxf(mx0, __shfl_xor_sync(0xffffffffu, mx0, 2));
        mx1 = fmaxf(mx1, __shfl_xor_sync(0xffffffffu, mx1, 1));
        mx1 = fmaxf(mx1, __shfl_xor_sync(0xffffffffu, mx1, 2));
        float a0 = __expf(m0 - mx0), a1 = __expf(m1 - mx1);
        m0 = mx0; m1 = mx1;

        float ls0 = 0.f, ls1 = 0.f;
        uint32_t pah[8][4], pal[8][4];
#pragma unroll
        for (int kj = 0; kj < 8; kj++) {
            float p00 = __expf(sacc[2 * kj][0] - m0);
            float p01 = __expf(sacc[2 * kj][1] - m0);
            float p02 = __expf(sacc[2 * kj][2] - m1);
            float p03 = __expf(sacc[2 * kj][3] - m1);
            float p10 = __expf(sacc[2 * kj + 1][0] - m0);
            float p11 = __expf(sacc[2 * kj + 1][1] - m0);
            float p12 = __expf(sacc[2 * kj + 1][2] - m1);
            float p13 = __expf(sacc[2 * kj + 1][3] - m1);
            ls0 += p00 + p01 + p10 + p11;
            ls1 += p02 + p03 + p12 + p13;
            pah[kj][0] = packh(p00, p01);
            pah[kj][1] = packh(p02, p03);
            pah[kj][2] = packh(p10, p11);
            pah[kj][3] = packh(p12, p13);
            float q00 = p00 - __half2float(__float2half(p00));
            float q01 = p01 - __half2float(__float2half(p01));
            float q02 = p02 - __half2float(__float2half(p02));
            float q03 = p03 - __half2float(__float2half(p03));
            float q10 = p10 - __half2float(__float2half(p10));
            float q11 = p11 - __half2float(__float2half(p11));
            float q12 = p12 - __half2float(__float2half(p12));
            float q13 = p13 - __half2float(__float2half(p13));
            pal[kj][0] = packh(q00, q01);
            pal[kj][1] = packh(q02, q03);
            pal[kj][2] = packh(q10, q11);
            pal[kj][3] = packh(q12, q13);
        }
        ls0 += __shfl_xor_sync(0xffffffffu, ls0, 1);
        ls0 += __shfl_xor_sync(0xffffffffu, ls0, 2);
        ls1 += __shfl_xor_sync(0xffffffffu, ls1, 1);
        ls1 += __shfl_xor_sync(0xffffffffu, ls1, 2);
        l0 = l0 * a0 + ls0;
        l1 = l1 * a1 + ls1;
#pragma unroll
        for (int dt = 0; dt < 8; dt++) {
            oacc[dt][0] *= a0; oacc[dt][1] *= a0;
            oacc[dt][2] *= a1; oacc[dt][3] *= a1;
        }

#pragma unroll
        for (int dt = 0; dt < 8; dt++) {
            int rowV = dt * 8 + (li & 7);
#pragma unroll
            for (int kj = 0; kj < 8; kj++) {
                uint32_t off = (uint32_t)((kj >> 2) * 8192) +
                               SWZ128((uint32_t)(rowV * 128 + (li >> 3) * 16 + (kj & 3) * 32));
                uint32_t vh2[2];
                ldsm_x2(vh2, kb + 16384 + off);
                mma16816f(oacc[dt], pah[kj], vh2);
                mma16816f(oacc[dt], pal[kj], vh2);
            }
        }
        __syncthreads();
    }

    float i0 = 1.f / l0, i1 = 1.f / l1;
    float* stg = (float*)at_smem;   // [128][66]
    int r0 = wid * 16 + (lane >> 2);
#pragma unroll
    for (int dt = 0; dt < 8; dt++) {
        int d = dt * 8 + (lane & 3) * 2;
        stg[r0 * 66 + d]           = oacc[dt][0] * i0;
        stg[r0 * 66 + d + 1]       = oacc[dt][1] * i0;
        stg[(r0 + 8) * 66 + d]     = oacc[dt][2] * i1;
        stg[(r0 + 8) * 66 + d + 1] = oacc[dt][3] * i1;
    }
    __syncthreads();
    for (int e = tid; e < 4096; e += 256) {
        int i = e >> 5, dp = (e & 31) * 2;
        __half2 hv = __floats2half2_rn(stg[i * 66 + dp], stg[i * 66 + dp + 1]);
        *(__half2*)&OutB[((long)b * 1024 + qt * 128 + i) * 256 + h * 64 + dp] = hv;
    }
}

// ---------------- launch ----------------
extern "C" void kernel_launch(void* const* d_in, const int* in_sizes, int n_in,
                              void* d_out, int out_size)
{
    const float* x      = (const float*)d_in[0];
    const float* cv1_w  = (const float*)d_in[1];
    const float* cv1_bn = (const float*)d_in[2];
    const float* cv2_w  = (const float*)d_in[3];
    const float* cv2_bn = (const float*)d_in[4];
    const float* mcv1w  = (const float*)d_in[5];
    const float* mcv1bn = (const float*)d_in[6];
    const float* mqkvw  = (const float*)d_in[7];
    const float* mrw    = (const float*)d_in[8];
    const float* mrh    = (const float*)d_in[9];
    const float* mcv2w  = (const float*)d_in[10];
    const float* mcv2bn = (const float*)d_in[11];
    float* out = (float*)d_out;

    float *cat, *scl, *bia;
    uint16_t *qkvH, *whi, *bhi, *blo;
    cudaGetSymbolAddress((void**)&cat,   g_cat);
    cudaGetSymbolAddress((void**)&qkvH,  g_qkvH);
    cudaGetSymbolAddress((void**)&scl,   g_scale);
    cudaGetSymbolAddress((void**)&bia,   g_bias);
    cudaGetSymbolAddress((void**)&whi,   g_Whi);
    cudaGetSymbolAddress((void**)&bhi,   g_Bhi);
    cudaGetSymbolAddress((void**)&blo,   g_Blo);

    cudaFuncSetAttribute(mgemm_kernel, cudaFuncAttributeMaxDynamicSharedMemorySize, MG_SMEM);
    cudaFuncSetAttribute(mgemm64_kernel_t<0>, cudaFuncAttributeMaxDynamicSharedMemorySize, MG64_SMEM);
    cudaFuncSetAttribute(mgemm64_kernel_t<1>, cudaFuncAttributeMaxDynamicSharedMemorySize, MG64_SMEM);
    cudaFuncSetAttribute(attn_mma_kernel, cudaFuncAttributeMaxDynamicSharedMemorySize, AT_SMEM);

    fold_bn_kernel<<<8, 256>>>(cv1_bn, cv2_bn, mcv1bn, mcv2bn);
    convW_all_kernel<<<(W_TOTAL + 255) / 256, 256>>>(cv1_w, mcv1w, mqkvw, mcv2w, cv2_w, whi);

    // ---- cv1: 512 -> 512, BN+SiLU -> fp32 cat[0:512) + catB columns [0:512) ----
    convB_kernel<<<dim3(32, 16, 8), dim3(32, 8)>>>(x, (long)512 * HW, 512, bhi + XB_OFF);
    mgemm_kernel<<<dim3(8, 4, 8), 256, MG_SMEM>>>(
        bhi + XB_OFF, whi + W_CV1, 512, cat, nullptr, (long)1024 * HW,
        bhi + CATB_OFF, 1024, 0,
        scl + 0, bia + 0, nullptr, 0, 1);

    for (int i = 0; i < 2; i++) {
        long yin  = (long)(i == 0 ? 256 : 512) * HW;
        long yout = (long)(512 + i * 256) * HW;
        long wConv = i ? W_CONV1 : W_CONV0;
        long wQkv  = i ? W_QKV1  : W_QKV0;
        long wCv2  = i ? W_CV2M1 : W_CV2M0;

        // z = cbs(yi, 3x3) as IMPLICIT GEMM, B = catB slice (row stride 1024, colBase 256*(i+1))
        mgemm64_kernel_t<1><<<dim3(16, 2, 8), 256, MG64_SMEM>>>(
            bhi + CATB_OFF, whi + wConv, 2304, 1024, 32 * (i + 1),
            nullptr, 0, bhi + ZB_OFF, 256, 0,
            scl + 1024 + i * 256, bia + 1024 + i * 256, nullptr, 0, 1);

        // qkv = conv1x1(z), 256 -> 768 (reads ZB); output fp16 qkvH
        mgemm_kernel<<<dim3(8, 6, 8), 256, MG_SMEM>>>(
            bhi + ZB_OFF, whi + wQkv, 256, nullptr, qkvH, (long)768 * HW,
            nullptr, 0, 0,
            nullptr, nullptr, nullptr, 0, 0);

        // attention operand conversion (fp16) + MMA flash attention -> fp16 B-layout ATB
        convAttn_kernel<<<dim3(32, 2, 32), dim3(32, 8)>>>(
            qkvH, mrw + (long)i * 8192, mrh + (long)i * 8192, bhi, blo);
        attn_mma_kernel<<<dim3(8, 4, 8), 256, AT_SMEM>>>(bhi, blo, bhi + ATB_OFF);

        // y_{i+2} = yi + silu(bn(conv1x1(attn))) (reads ATB) -> fp32 cat slice + catB slice
        mgemm64_kernel_t<0><<<dim3(16, 2, 8), 256, MG64_SMEM>>>(
            bhi + ATB_OFF, whi + wCv2, 256, 256, 0,
            cat + yout, (long)1024 * HW, bhi + CATB_OFF, 1024, 512 + i * 256,
            scl + 1536 + i * 256, bia + 1536 + i * 256, cat + yin, (long)1024 * HW, 1);
    }

    // ---- final: 1024 -> 512, BN+SiLU, fp32 out; B = catB directly ----
    mgemm_kernel<<<dim3(8, 4, 8), 256, MG_SMEM>>>(
        bhi + CATB_OFF, whi + W_FIN, 1024, out, nullptr, (long)512 * HW,
        nullptr, 0, 0,
        scl + 512, bia + 512, nullptr, 0, 1);
}